// round 5
// baseline (speedup 1.0000x reference)
#include <cuda_runtime.h>
#include <cuda_bf16.h>
#include <math.h>

#define H_   16
#define KV_  8
#define D_   128
#define HID_ 2048
#define Q_   1024
#define S_   8192

// ---------------- scratch (device globals: no allocation allowed) ----------------
__device__ float g_q   [HID_ * Q_];        // q projection  [2048][1024]
__device__ float g_k   [KV_ * D_ * Q_];    // k projection  [1024][1024]
__device__ float g_v   [KV_ * D_ * Q_];    // v projection  [1024][1024]
__device__ float g_qt  [H_ * Q_ * D_];     // q after RoPE, [h][i][d], pre-scaled by 1/sqrt(D)
__device__ float g_knew[KV_ * Q_ * D_];    // new K after RoPE, [kv][i][d]
__device__ float g_vnew[KV_ * Q_ * D_];    // new V transposed, [kv][i][d]
__device__ float g_attnT[Q_ * HID_];       // attention out, transposed [q][c]

// ---------------- SGEMM: C[M,N] = A[M,K] * B + bias, 64x64x16 tiles ----------------
// BT=false: B is [K][N] row-major.  BT=true: B is [N][K] row-major (B transposed).
template<bool BT>
__global__ __launch_bounds__(256)
void sgemm_kernel(const float* __restrict__ A, const float* __restrict__ B,
                  const float* __restrict__ bias, float* __restrict__ C,
                  int M, int N, int K)
{
    __shared__ float As[16][68];
    __shared__ float Bs[16][68];
    const int tid = threadIdx.x;
    const int tx = tid & 15, ty = tid >> 4;
    const int m0 = blockIdx.y * 64, n0 = blockIdx.x * 64;

    float acc[4][4];
#pragma unroll
    for (int a = 0; a < 4; a++)
#pragma unroll
        for (int b = 0; b < 4; b++) acc[a][b] = 0.f;

    const int arow = tid >> 2;          // 0..63
    const int akc  = (tid & 3) * 4;     // 0,4,8,12

    for (int k0 = 0; k0 < K; k0 += 16) {
        // A tile: 64 rows x 16 k, float4 loads, transposed scalar stores
        float4 a4 = *(const float4*)&A[(size_t)(m0 + arow) * K + k0 + akc];
        As[akc + 0][arow] = a4.x; As[akc + 1][arow] = a4.y;
        As[akc + 2][arow] = a4.z; As[akc + 3][arow] = a4.w;
        if (!BT) {
            int brow = tid >> 4;            // 0..15
            int bnc  = (tid & 15) * 4;      // 0..60
            float4 b4 = *(const float4*)&B[(size_t)(k0 + brow) * N + n0 + bnc];
            *(float4*)&Bs[brow][bnc] = b4;  // row stride 68 floats = 272B, 16B aligned
        } else {
            float4 b4 = *(const float4*)&B[(size_t)(n0 + arow) * K + k0 + akc];
            Bs[akc + 0][arow] = b4.x; Bs[akc + 1][arow] = b4.y;
            Bs[akc + 2][arow] = b4.z; Bs[akc + 3][arow] = b4.w;
        }
        __syncthreads();
#pragma unroll
        for (int kk = 0; kk < 16; kk++) {
            float ar[4], br[4];
#pragma unroll
            for (int x = 0; x < 4; x++) ar[x] = As[kk][ty + 16 * x];
#pragma unroll
            for (int x = 0; x < 4; x++) br[x] = Bs[kk][tx + 16 * x];
#pragma unroll
            for (int a = 0; a < 4; a++)
#pragma unroll
                for (int b = 0; b < 4; b++)
                    acc[a][b] = fmaf(ar[a], br[b], acc[a][b]);
        }
        __syncthreads();
    }
#pragma unroll
    for (int a = 0; a < 4; a++) {
        int m = m0 + ty + 16 * a;
        float bv = bias ? bias[m] : 0.f;
#pragma unroll
        for (int b = 0; b < 4; b++)
            C[(size_t)m * N + n0 + tx + 16 * b] = acc[a][b] + bv;
    }
}

// -------- RoPE + transpose: src [nh*128][Q] -> dst [nh][Q][128], optional rope --------
// cos/sin tables in (Q, D) layout (the non-transposed ones): fully coalesced.
__global__ __launch_bounds__(256)
void rope_transpose_kernel(const float* __restrict__ src, const float* __restrict__ cosQD,
                           const float* __restrict__ sinQD, float* __restrict__ dst,
                           float scale, int do_rope)
{
    __shared__ float tile[128][33];
    const int tx = threadIdx.x, ty = threadIdx.y;   // 32 x 8
    const int i0 = blockIdx.x * 32;
    const int h  = blockIdx.y;
#pragma unroll
    for (int r = 0; r < 16; r++) {
        int row = r * 8 + ty;   // 0..127 (d)
        tile[row][tx] = src[(size_t)(h * 128 + row) * Q_ + i0 + tx];
    }
    __syncthreads();
    const int t = ty * 32 + tx;
#pragma unroll
    for (int r = 0; r < 16; r++) {
        int idx = r * 256 + t;
        int d = idx & 127, i = idx >> 7;
        float v = tile[d][i];
        float out;
        if (do_rope) {
            float o = (d < 64) ? -tile[d + 64][i] : tile[d - 64][i];
            float c = cosQD[(size_t)(i0 + i) * 128 + d];
            float s = sinQD[(size_t)(i0 + i) * 128 + d];
            out = (v * c + o * s) * scale;
        } else {
            out = v;
        }
        dst[(size_t)(h * Q_ + i0 + i) * 128 + d] = out;
    }
}

// ---------------- flash attention: BQ=64 queries x BS=32 keys per step ----------------
// grid (Q/64, H). q pre-scaled by 1/sqrt(D). Causal mask analytic (== reference mask).
// K/V gathered from cache for s<cpos or s>=cpos+Q, else from RoPE'd new K/V.
// Output written transposed [q][h*128+d] with coalesced float4 stores.
__global__ __launch_bounds__(256)
void attn_kernel(const float* __restrict__ qt, const float* __restrict__ knew,
                 const float* __restrict__ vnew, const float* __restrict__ kcache,
                 const float* __restrict__ vcache, const int* __restrict__ cpos_p,
                 float* __restrict__ outT)
{
    extern __shared__ float sm[];
    float* sQ   = sm;                   // 64*128
    float* sK   = sQ + 64 * 128;        // 32*129 (padded)
    float* sV   = sK + 32 * 129;        // 32*128
    float* sS   = sV + 32 * 128;        // 64*33  (probs)
    float* m_s  = sS + 64 * 33;         // 64
    float* l_s  = m_s + 64;             // 64
    float* sc_s = l_s + 64;             // 64

    const int tid = threadIdx.x;
    const int q0  = blockIdx.x * 64;
    const int h   = blockIdx.y;
    const int kv  = h >> 1;             // GQA: G = H/KV = 2
    const int cpos = cpos_p[0];

    if (tid < 64) { m_s[tid] = -1e30f; l_s[tid] = 0.f; }

    // load Q tile (64 x 128), coalesced float4
#pragma unroll
    for (int r = 0; r < 8; r++) {
        int idx = r * 256 + tid;
        int i = idx >> 5, c4 = (idx & 31) << 2;
        *(float4*)&sQ[i * 128 + c4] =
            *(const float4*)&qt[(size_t)(h * Q_ + q0 + i) * 128 + c4];
    }

    const int lane = tid & 31, w = tid >> 5;    // PV mapping: d = lane*4, rows i = w+8*wi
    const int tx = tid & 15, ty = tid >> 4;     // score mapping: j = tx+16b, i = ty+16a

    float acc[8][4];
#pragma unroll
    for (int a = 0; a < 8; a++)
#pragma unroll
        for (int c = 0; c < 4; c++) acc[a][c] = 0.f;

    int nblk = (cpos + q0 + 63) / 32 + 1;       // last visible key = cpos + q0 + 63
    if (nblk > S_ / 32) nblk = S_ / 32;

    for (int sb = 0; sb < nblk; sb++) {
        const int s0 = sb * 32;
        __syncthreads();    // protect sK/sV/sS reuse + m_s/l_s ordering

        // load K (scalar stores into padded rows) and V (float4) tiles
#pragma unroll
        for (int r = 0; r < 4; r++) {
            int idx = r * 256 + tid;
            int j = idx >> 5, c4 = (idx & 31) << 2;
            int s = s0 + j;
            bool is_new = (s >= cpos) && (s < cpos + Q_);
            const float* srck = is_new ? &knew[(size_t)(kv * Q_ + (s - cpos)) * 128]
                                       : &kcache[(size_t)(kv * S_ + s) * 128];
            float4 kk4 = *(const float4*)&srck[c4];
            sK[j * 129 + c4 + 0] = kk4.x; sK[j * 129 + c4 + 1] = kk4.y;
            sK[j * 129 + c4 + 2] = kk4.z; sK[j * 129 + c4 + 3] = kk4.w;
            const float* srcv = is_new ? &vnew[(size_t)(kv * Q_ + (s - cpos)) * 128]
                                       : &vcache[(size_t)(kv * S_ + s) * 128];
            *(float4*)&sV[j * 128 + c4] = *(const float4*)&srcv[c4];
        }
        __syncthreads();

        // ---- scores: 64x32, each thread 4 rows x 2 cols ----
        float scr[4][2];
#pragma unroll
        for (int a = 0; a < 4; a++) { scr[a][0] = 0.f; scr[a][1] = 0.f; }
#pragma unroll 4
        for (int d = 0; d < 128; d++) {
            float k0v = sK[tx * 129 + d];
            float k1v = sK[(tx + 16) * 129 + d];
#pragma unroll
            for (int a = 0; a < 4; a++) {
                float qv = sQ[(ty + 16 * a) * 128 + d];
                scr[a][0] = fmaf(qv, k0v, scr[a][0]);
                scr[a][1] = fmaf(qv, k1v, scr[a][1]);
            }
        }

        // ---- mask + online softmax (rows owned by 16-lane half-warps) ----
#pragma unroll
        for (int a = 0; a < 4; a++) {
            int i = ty + 16 * a;
            int lim = cpos + q0 + i;                 // key s visible iff s <= lim
            if (s0 + tx      > lim) scr[a][0] = -1e30f;
            if (s0 + tx + 16 > lim) scr[a][1] = -1e30f;
            float mx = fmaxf(scr[a][0], scr[a][1]);
#pragma unroll
            for (int o = 8; o >= 1; o >>= 1)
                mx = fmaxf(mx, __shfl_xor_sync(0xffffffffu, mx, o));
            float m_old = m_s[i];
            float m_new = fmaxf(m_old, mx);
            float p0 = __expf(scr[a][0] - m_new);
            float p1 = __expf(scr[a][1] - m_new);
            sS[i * 33 + tx]      = p0;
            sS[i * 33 + tx + 16] = p1;
            float ls = p0 + p1;
#pragma unroll
            for (int o = 8; o >= 1; o >>= 1)
                ls += __shfl_xor_sync(0xffffffffu, ls, o);
            if (tx == 0) {
                float scl = __expf(m_old - m_new);
                sc_s[i] = scl;
                l_s[i]  = l_s[i] * scl + ls;
                m_s[i]  = m_new;
            }
        }
        __syncthreads();

        // ---- PV accumulate: thread owns d-chunk lane*4, rows w+8*wi ----
#pragma unroll
        for (int wi = 0; wi < 8; wi++) {
            float s = sc_s[w + 8 * wi];
            acc[wi][0] *= s; acc[wi][1] *= s; acc[wi][2] *= s; acc[wi][3] *= s;
        }
#pragma unroll 4
        for (int j = 0; j < 32; j++) {
            float4 v4 = *(const float4*)&sV[j * 128 + lane * 4];
#pragma unroll
            for (int wi = 0; wi < 8; wi++) {
                float p = sS[(w + 8 * wi) * 33 + j];
                acc[wi][0] = fmaf(p, v4.x, acc[wi][0]);
                acc[wi][1] = fmaf(p, v4.y, acc[wi][1]);
                acc[wi][2] = fmaf(p, v4.z, acc[wi][2]);
                acc[wi][3] = fmaf(p, v4.w, acc[wi][3]);
            }
        }
    }
    __syncthreads();

    // epilogue: normalize + coalesced float4 stores into transposed layout [q][c]
#pragma unroll
    for (int wi = 0; wi < 8; wi++) {
        int i = w + 8 * wi;
        float inv = 1.f / l_s[i];
        float4 o4 = make_float4(acc[wi][0] * inv, acc[wi][1] * inv,
                                acc[wi][2] * inv, acc[wi][3] * inv);
        *(float4*)&outT[(size_t)(q0 + i) * HID_ + h * 128 + lane * 4] = o4;
    }
}

// ---------------- launch ----------------
extern "C" void kernel_launch(void* const* d_in, const int* in_sizes, int n_in,
                              void* d_out, int out_size)
{
    const float* hidden = (const float*)d_in[0];   // (1,2048,1,1024)
    const float* cosQD  = (const float*)d_in[1];   // (1,1,Q,D)
    const float* sinQD  = (const float*)d_in[2];   // (1,1,Q,D)
    // d_in[3]=cos_t, d_in[4]=sin_t, d_in[5]=attention_mask: unused (mask is analytic causal)
    const float* kcache = (const float*)d_in[6];   // (1,KV,S,D)
    const float* vcache = (const float*)d_in[7];
    const float* Wq = (const float*)d_in[8];
    const float* bq = (const float*)d_in[9];
    const float* Wk = (const float*)d_in[10];
    const float* bk = (const float*)d_in[11];
    const float* Wv = (const float*)d_in[12];
    const float* bv = (const float*)d_in[13];
    const float* Wo = (const float*)d_in[14];
    const int*   cpos = (const int*)d_in[15];      // 4096 (little-endian: int32/int64 both ok)
    float* out = (float*)d_out;

    float *pq, *pk, *pv, *pqt, *pkn, *pvn, *pat;
    cudaGetSymbolAddress((void**)&pq,  g_q);
    cudaGetSymbolAddress((void**)&pk,  g_k);
    cudaGetSymbolAddress((void**)&pv,  g_v);
    cudaGetSymbolAddress((void**)&pqt, g_qt);
    cudaGetSymbolAddress((void**)&pkn, g_knew);
    cudaGetSymbolAddress((void**)&pvn, g_vnew);
    cudaGetSymbolAddress((void**)&pat, g_attnT);

    // 1) projections (C = W * hidden + b), hidden is [HID][Q]
    sgemm_kernel<false><<<dim3(Q_ / 64, HID_ / 64), 256>>>(Wq, hidden, bq, pq, HID_, Q_, HID_);
    sgemm_kernel<false><<<dim3(Q_ / 64, (KV_ * D_) / 64), 256>>>(Wk, hidden, bk, pk, KV_ * D_, Q_, HID_);
    sgemm_kernel<false><<<dim3(Q_ / 64, (KV_ * D_) / 64), 256>>>(Wv, hidden, bv, pv, KV_ * D_, Q_, HID_);

    // 2) RoPE + transpose to [head][q][d]; q gets 1/sqrt(D) folded in
    rope_transpose_kernel<<<dim3(Q_ / 32, H_),  dim3(32, 8)>>>(pq, cosQD, sinQD, pqt, 0.08838834764831845f, 1);
    rope_transpose_kernel<<<dim3(Q_ / 32, KV_), dim3(32, 8)>>>(pk, cosQD, sinQD, pkn, 1.0f, 1);
    rope_transpose_kernel<<<dim3(Q_ / 32, KV_), dim3(32, 8)>>>(pv, nullptr, nullptr, pvn, 1.0f, 0);

    // 3) flash attention over cache + new KV
    const size_t ATTN_SMEM = (size_t)(64 * 128 + 32 * 129 + 32 * 128 + 64 * 33 + 3 * 64) * sizeof(float);
    cudaFuncSetAttribute(attn_kernel, cudaFuncAttributeMaxDynamicSharedMemorySize, (int)ATTN_SMEM);
    attn_kernel<<<dim3(Q_ / 64, H_), 256, ATTN_SMEM>>>(pqt, pkn, pvn, kcache, vcache, cpos, pat);

    // 4) output projection: out = Wo * attn, attn stored transposed [q][c]
    sgemm_kernel<true><<<dim3(Q_ / 64, HID_ / 64), 256>>>(Wo, pat, nullptr, out, HID_, Q_, HID_);
}

// round 6
// speedup vs baseline: 2.6908x; 2.6908x over previous
#include <cuda_runtime.h>
#include <cuda_bf16.h>
#include <math.h>

typedef __nv_bfloat16 bf16;
#define H_   16
#define KV_  8
#define D_   128
#define HID_ 2048
#define Q_   1024
#define S_   8192
#define K3_  6144

// ---------------- device-global scratch (no allocation allowed) ----------------
__device__ float g_q[HID_*Q_];
__device__ float g_k[KV_*D_*Q_];
__device__ float g_v[KV_*D_*Q_];
__device__ float g_knew[KV_*Q_*D_];
__device__ float g_vnew[KV_*Q_*D_];
__device__ bf16  g_qhi[H_*Q_*D_],  g_qlo[H_*Q_*D_];
__device__ bf16  g_khi[KV_*S_*D_], g_klo[KV_*S_*D_];
__device__ bf16  g_vhi[KV_*S_*D_], g_vlo[KV_*S_*D_];
__device__ bf16  g_WqPk[(size_t)HID_*K3_];
__device__ bf16  g_WkPk[(size_t)KV_*D_*K3_];
__device__ bf16  g_WvPk[(size_t)KV_*D_*K3_];
__device__ bf16  g_WoPk[(size_t)HID_*K3_];
__device__ bf16  g_hidT[(size_t)Q_*K3_];
__device__ bf16  g_attnT[(size_t)Q_*K3_];

// ---------------- PTX helpers ----------------
__device__ __forceinline__ void ldsm4(unsigned &r0,unsigned &r1,unsigned &r2,unsigned &r3,unsigned a){
    asm volatile("ldmatrix.sync.aligned.m8n8.x4.shared.b16 {%0,%1,%2,%3},[%4];"
                 :"=r"(r0),"=r"(r1),"=r"(r2),"=r"(r3):"r"(a));
}
__device__ __forceinline__ void ldsm4t(unsigned &r0,unsigned &r1,unsigned &r2,unsigned &r3,unsigned a){
    asm volatile("ldmatrix.sync.aligned.m8n8.x4.trans.shared.b16 {%0,%1,%2,%3},[%4];"
                 :"=r"(r0),"=r"(r1),"=r"(r2),"=r"(r3):"r"(a));
}
__device__ __forceinline__ void mma16816(float c[4], const unsigned a[4], unsigned b0, unsigned b1){
    asm volatile("mma.sync.aligned.m16n8k16.row.col.f32.bf16.bf16.f32 "
                 "{%0,%1,%2,%3},{%4,%5,%6,%7},{%8,%9},{%0,%1,%2,%3};"
                 :"+f"(c[0]),"+f"(c[1]),"+f"(c[2]),"+f"(c[3])
                 :"r"(a[0]),"r"(a[1]),"r"(a[2]),"r"(a[3]),"r"(b0),"r"(b1));
}
__device__ __forceinline__ void cpa16(unsigned s, const void* g){
    asm volatile("cp.async.cg.shared.global [%0],[%1],16;"::"r"(s),"l"(g));
}
#define CPC()  asm volatile("cp.async.commit_group;")
#define CPW0() asm volatile("cp.async.wait_group 0;")
#define CPW1() asm volatile("cp.async.wait_group 1;")

__device__ __forceinline__ void hilo2(float x, float y, unsigned &hi, unsigned &lo){
    bf16 hx=__float2bfloat16_rn(x), hy=__float2bfloat16_rn(y);
    __nv_bfloat162 hp=__halves2bfloat162(hx,hy); hi=*reinterpret_cast<unsigned*>(&hp);
    bf16 lx=__float2bfloat16_rn(x-__bfloat162float(hx));
    bf16 ly=__float2bfloat16_rn(y-__bfloat162float(hy));
    __nv_bfloat162 lp=__halves2bfloat162(lx,ly); lo=*reinterpret_cast<unsigned*>(&lp);
}

// ---------------- prep: weight A-pack [hi|lo|hi] ----------------
__global__ __launch_bounds__(256)
void splitA_kernel(const float* __restrict__ W, bf16* __restrict__ dst, int total4){
    int idx = blockIdx.x*256 + threadIdx.x;
    if (idx >= total4) return;
    size_t lin = (size_t)idx*4;
    int col = (int)(lin & (HID_-1));
    size_t row = lin >> 11;
    float4 w = *(const float4*)(W + lin);
    unsigned h0,l0,h1,l1;
    hilo2(w.x, w.y, h0, l0); hilo2(w.z, w.w, h1, l1);
    size_t b = row*K3_ + col;
    *(uint2*)(dst+b)          = make_uint2(h0,h1);
    *(uint2*)(dst+b+HID_)     = make_uint2(l0,l1);
    *(uint2*)(dst+b+2*HID_)   = make_uint2(h0,h1);
}

// ---------------- prep: hidden [2048][1024] -> hidT B-pack [1024][6144] [hi|hi|lo] ----------------
__global__ __launch_bounds__(256)
void transpose_splitB_kernel(const float* __restrict__ src, bf16* __restrict__ dst){
    __shared__ float t[32][33];
    const int tx=threadIdx.x, ty=threadIdx.y;          // 32 x 8
    const int n0=blockIdx.x*32, k0=blockIdx.y*32;
#pragma unroll
    for (int r=0;r<4;r++)
        t[ty+8*r][tx] = src[(size_t)(k0+ty+8*r)*Q_ + n0+tx];
    __syncthreads();
#pragma unroll
    for (int r=0;r<4;r++){
        int n = ty+8*r;
        float v = t[tx][n];
        bf16 hb = __float2bfloat16_rn(v);
        bf16 lb = __float2bfloat16_rn(v - __bfloat162float(hb));
        size_t b = (size_t)(n0+n)*K3_ + k0+tx;
        dst[b] = hb; dst[b+HID_] = hb; dst[b+2*HID_] = lb;
    }
}

// ---------------- RoPE + transpose (fp32 out) for new K/V ----------------
__global__ __launch_bounds__(256)
void rope_transpose_kernel(const float* __restrict__ src, const float* __restrict__ cosQD,
                           const float* __restrict__ sinQD, float* __restrict__ dst, int do_rope){
    __shared__ float tile[128][33];
    const int tx=threadIdx.x, ty=threadIdx.y;          // 32 x 8
    const int i0=blockIdx.x*32, h=blockIdx.y;
#pragma unroll
    for (int r=0;r<16;r++)
        tile[r*8+ty][tx] = src[(size_t)(h*128 + r*8+ty)*Q_ + i0+tx];
    __syncthreads();
    const int t = ty*32+tx;
#pragma unroll
    for (int r=0;r<16;r++){
        int idx = r*256 + t;
        int d = idx & 127, i = idx >> 7;
        float v = tile[d][i], out;
        if (do_rope){
            float o = (d<64) ? -tile[d+64][i] : tile[d-64][i];
            out = v*cosQD[(size_t)(i0+i)*128+d] + o*sinQD[(size_t)(i0+i)*128+d];
        } else out = v;
        dst[(size_t)(h*Q_ + i0+i)*128 + d] = out;
    }
}

// ---------------- RoPE + transpose + hi/lo split for Q (folds 1/sqrt(D)) ----------------
__global__ __launch_bounds__(256)
void rope_q_split_kernel(const float* __restrict__ src, const float* __restrict__ cosQD,
                         const float* __restrict__ sinQD, bf16* __restrict__ qhi,
                         bf16* __restrict__ qlo, float scale){
    __shared__ float tile[128][33];
    const int tx=threadIdx.x, ty=threadIdx.y;
    const int i0=blockIdx.x*32, h=blockIdx.y;
#pragma unroll
    for (int r=0;r<16;r++)
        tile[r*8+ty][tx] = src[(size_t)(h*128 + r*8+ty)*Q_ + i0+tx];
    __syncthreads();
    const int t = ty*32+tx;
#pragma unroll
    for (int r=0;r<16;r++){
        int idx = r*256 + t;
        int d = idx & 127, i = idx >> 7;
        float v = tile[d][i];
        float o = (d<64) ? -tile[d+64][i] : tile[d-64][i];
        float out = (v*cosQD[(size_t)(i0+i)*128+d] + o*sinQD[(size_t)(i0+i)*128+d])*scale;
        bf16 hb = __float2bfloat16_rn(out);
        bf16 lb = __float2bfloat16_rn(out - __bfloat162float(hb));
        size_t di = ((size_t)h*Q_ + i0+i)*128 + d;
        qhi[di] = hb; qlo[di] = lb;
    }
}

// ---------------- merged KV cache -> bf16 hi/lo [kv][S][D] ----------------
__global__ __launch_bounds__(256)
void merge_split_kv_kernel(const float* __restrict__ kc_, const float* __restrict__ vc_,
                           const float* __restrict__ kn, const float* __restrict__ vn,
                           const int* __restrict__ cposp,
                           bf16* __restrict__ khi, bf16* __restrict__ klo,
                           bf16* __restrict__ vhi, bf16* __restrict__ vlo){
    int idx = blockIdx.x*256 + threadIdx.x;
    const int total = KV_*S_*D_/4;
    if (idx >= total) return;
    int cpos = cposp[0];
    size_t lin = (size_t)idx*4;
    int s  = (int)((lin>>7) & (S_-1));
    int kv = (int)(lin>>20);
    int d  = (int)(lin & 127);
    bool nw = (s >= cpos) && (s < cpos + Q_);
    size_t nlin = ((size_t)kv*Q_ + (s-cpos))*128 + d;
    float4 k4 = nw ? *(const float4*)(kn+nlin) : *(const float4*)(kc_+lin);
    float4 v4 = nw ? *(const float4*)(vn+nlin) : *(const float4*)(vc_+lin);
    unsigned h0,l0,h1,l1;
    hilo2(k4.x,k4.y,h0,l0); hilo2(k4.z,k4.w,h1,l1);
    *(uint2*)(khi+lin)=make_uint2(h0,h1); *(uint2*)(klo+lin)=make_uint2(l0,l1);
    hilo2(v4.x,v4.y,h0,l0); hilo2(v4.z,v4.w,h1,l1);
    *(uint2*)(vhi+lin)=make_uint2(h0,h1); *(uint2*)(vlo+lin)=make_uint2(l0,l1);
}

// ---------------- packed-K bf16 GEMM: C[M][1024] = A[M][6144] * B[1024][6144]^T (+bias) ----------------
__global__ __launch_bounds__(256)
void gemm_pk_kernel(const bf16* __restrict__ A, const bf16* __restrict__ B,
                    const float* __restrict__ bias, float* __restrict__ C){
    __shared__ bf16 sA[2][128*40];
    __shared__ bf16 sB[2][128*40];
    const int tid=threadIdx.x, lane=tid&31, warp=tid>>5;
    const int wm = warp>>1, wn = warp&1;
    const int m0 = blockIdx.y*128, n0 = blockIdx.x*128;
    const unsigned uA=(unsigned)__cvta_generic_to_shared(&sA[0][0]);
    const unsigned uB=(unsigned)__cvta_generic_to_shared(&sB[0][0]);

    float acc[2][8][4];
#pragma unroll
    for (int a=0;a<2;a++)
#pragma unroll
        for (int b=0;b<8;b++)
#pragma unroll
            for (int c=0;c<4;c++) acc[a][b][c]=0.f;

    auto load=[&](int st,int k0){
#pragma unroll
        for (int i=0;i<2;i++){
            int c = tid + i*256;
            int row = c>>2, seg = c&3;
            cpa16(uA + (st*5120 + row*40 + seg*8)*2, A + (size_t)(m0+row)*K3_ + k0 + seg*8);
            cpa16(uB + (st*5120 + row*40 + seg*8)*2, B + (size_t)(n0+row)*K3_ + k0 + seg*8);
        }
    };
    load(0,0); CPC();

    for (int kt=0;kt<192;kt++){
        int st = kt&1;
        if (kt<191){ load(st^1,(kt+1)*32); CPC(); CPW1(); } else { CPW0(); }
        __syncthreads();
#pragma unroll
        for (int kh=0;kh<2;kh++){
            unsigned a0[4], a1[4];
            unsigned ao = (unsigned)((st*5120 + (wm*32+(lane&15))*40 + kh*16 + (lane>>4)*8)*2);
            ldsm4(a0[0],a0[1],a0[2],a0[3], uA+ao);
            ldsm4(a1[0],a1[1],a1[2],a1[3], uA+ao + 16*40*2);
            unsigned bf_[8][2];
#pragma unroll
            for (int nt=0;nt<4;nt++){
                unsigned bo = (unsigned)((st*5120 + (wn*64+nt*16+(lane&15))*40 + kh*16 + (lane>>4)*8)*2);
                unsigned r0,r1,r2,r3;
                ldsm4(r0,r1,r2,r3, uB+bo);
                bf_[2*nt][0]=r0; bf_[2*nt][1]=r2; bf_[2*nt+1][0]=r1; bf_[2*nt+1][1]=r3;
            }
#pragma unroll
            for (int nf=0;nf<8;nf++){
                mma16816(acc[0][nf], a0, bf_[nf][0], bf_[nf][1]);
                mma16816(acc[1][nf], a1, bf_[nf][0], bf_[nf][1]);
            }
        }
        __syncthreads();
    }
#pragma unroll
    for (int mf=0;mf<2;mf++)
#pragma unroll
        for (int nf=0;nf<8;nf++){
            int row = m0 + wm*32 + mf*16 + (lane>>2);
            int col = n0 + wn*64 + nf*8 + (lane&3)*2;
            float b0 = bias ? bias[row]   : 0.f;
            float b1 = bias ? bias[row+8] : 0.f;
            C[(size_t)row*Q_ + col]       = acc[mf][nf][0] + b0;
            C[(size_t)row*Q_ + col + 1]   = acc[mf][nf][1] + b0;
            C[(size_t)(row+8)*Q_ + col]   = acc[mf][nf][2] + b1;
            C[(size_t)(row+8)*Q_ + col+1] = acc[mf][nf][3] + b1;
        }
}

// ---------------- flash attention with bf16 hi/lo MMA ----------------
// BQ=64 (4 warps x 16 rows), BS=64. Writes Wo B-pack [hi|hi|lo] into attnT[q][6144].
__global__ __launch_bounds__(128)
void attn_kernel(const bf16* __restrict__ qhi, const bf16* __restrict__ qlo,
                 const bf16* __restrict__ khi, const bf16* __restrict__ klo,
                 const bf16* __restrict__ vhi, const bf16* __restrict__ vlo,
                 const int* __restrict__ cposp, bf16* __restrict__ attnT){
    extern __shared__ bf16 smem[];
    const int TS = 64*136;   // 8704 elems per tile
    const int tid=threadIdx.x, lane=tid&31, w=tid>>5;
    const int q0=blockIdx.x*64, h=blockIdx.y, kv=h>>1;
    const int cpos = cposp[0];
    const unsigned sb=(unsigned)__cvta_generic_to_shared(smem);
    const unsigned uQh=sb, uQl=sb+TS*2, uKh=sb+2*TS*2, uKl=sb+3*TS*2, uVh=sb+4*TS*2, uVl=sb+5*TS*2;

    // load Q tiles (hi & lo)
#pragma unroll
    for (int i=0;i<8;i++){
        int c = tid + i*128;
        int row = c>>4, seg = c&15;
        size_t gq = ((size_t)h*Q_ + q0 + row)*128 + seg*8;
        unsigned so = (unsigned)((row*136 + seg*8)*2);
        cpa16(uQh+so, qhi+gq);
        cpa16(uQl+so, qlo+gq);
    }
    CPC(); CPW0(); __syncthreads();

    float out[16][4];
#pragma unroll
    for (int a=0;a<16;a++)
#pragma unroll
        for (int c=0;c<4;c++) out[a][c]=0.f;
    float m0=-1e30f, m1=-1e30f, l0=0.f, l1=0.f;
    const int r0 = lane>>2, qb = q0 + w*16;

    int nblk = (cpos + q0 + 63)/64 + 1;
    if (nblk > S_/64) nblk = S_/64;

    for (int sbk=0; sbk<nblk; sbk++){
        const int s0 = sbk*64;
        __syncthreads();
#pragma unroll
        for (int i=0;i<8;i++){
            int c = tid + i*128;
            int row = c>>4, seg = c&15;
            size_t gk = ((size_t)kv*S_ + s0 + row)*128 + seg*8;
            unsigned so = (unsigned)((row*136 + seg*8)*2);
            cpa16(uKh+so, khi+gk); cpa16(uKl+so, klo+gk);
            cpa16(uVh+so, vhi+gk); cpa16(uVl+so, vlo+gk);
        }
        CPC(); CPW0(); __syncthreads();

        // ---- scores: Qhi*Khi + Qlo*Khi + Qhi*Klo ----
        float sc[8][4];
#pragma unroll
        for (int a=0;a<8;a++)
#pragma unroll
            for (int c=0;c<4;c++) sc[a][c]=0.f;
#pragma unroll
        for (int kd=0;kd<8;kd++){
            unsigned ah[4], al[4];
            unsigned qo = (unsigned)(((w*16+(lane&15))*136 + kd*16 + (lane>>4)*8)*2);
            ldsm4(ah[0],ah[1],ah[2],ah[3], uQh+qo);
            ldsm4(al[0],al[1],al[2],al[3], uQl+qo);
#pragma unroll
            for (int nt=0;nt<4;nt++){
                unsigned ko = (unsigned)(((nt*16+(lane&15))*136 + kd*16 + (lane>>4)*8)*2);
                unsigned h0,h1,h2,h3, e0,e1,e2,e3;
                ldsm4(h0,h1,h2,h3, uKh+ko);
                ldsm4(e0,e1,e2,e3, uKl+ko);
                mma16816(sc[2*nt],   ah, h0,h2);
                mma16816(sc[2*nt],   al, h0,h2);
                mma16816(sc[2*nt],   ah, e0,e2);
                mma16816(sc[2*nt+1], ah, h1,h3);
                mma16816(sc[2*nt+1], al, h1,h3);
                mma16816(sc[2*nt+1], ah, e1,e3);
            }
        }

        // ---- causal mask (only when block straddles the diagonal) ----
        if (s0 + 63 > cpos + qb){
            int lim0 = cpos + qb + r0, lim1 = lim0 + 8;
#pragma unroll
            for (int nf=0;nf<8;nf++){
                int j = s0 + nf*8 + 2*(lane&3);
                if (j   > lim0) sc[nf][0] = -1e30f;
                if (j+1 > lim0) sc[nf][1] = -1e30f;
                if (j   > lim1) sc[nf][2] = -1e30f;
                if (j+1 > lim1) sc[nf][3] = -1e30f;
            }
        }

        // ---- online softmax (rows r0, r0+8; quad reduce over lanes xor 1,2) ----
        float mx0=-1e30f, mx1=-1e30f;
#pragma unroll
        for (int nf=0;nf<8;nf++){
            mx0 = fmaxf(mx0, fmaxf(sc[nf][0], sc[nf][1]));
            mx1 = fmaxf(mx1, fmaxf(sc[nf][2], sc[nf][3]));
        }
        mx0 = fmaxf(mx0, __shfl_xor_sync(0xffffffffu, mx0, 1));
        mx0 = fmaxf(mx0, __shfl_xor_sync(0xffffffffu, mx0, 2));
        mx1 = fmaxf(mx1, __shfl_xor_sync(0xffffffffu, mx1, 1));
        mx1 = fmaxf(mx1, __shfl_xor_sync(0xffffffffu, mx1, 2));
        float n0_ = fmaxf(m0, mx0), n1_ = fmaxf(m1, mx1);
        float s0f = __expf(m0 - n0_), s1f = __expf(m1 - n1_);
        m0 = n0_; m1 = n1_;
        float ps0 = 0.f, ps1 = 0.f;
#pragma unroll
        for (int nf=0;nf<8;nf++){
            sc[nf][0] = __expf(sc[nf][0] - m0); ps0 += sc[nf][0];
            sc[nf][1] = __expf(sc[nf][1] - m0); ps0 += sc[nf][1];
            sc[nf][2] = __expf(sc[nf][2] - m1); ps1 += sc[nf][2];
            sc[nf][3] = __expf(sc[nf][3] - m1); ps1 += sc[nf][3];
        }
        ps0 += __shfl_xor_sync(0xffffffffu, ps0, 1);
        ps0 += __shfl_xor_sync(0xffffffffu, ps0, 2);
        ps1 += __shfl_xor_sync(0xffffffffu, ps1, 1);
        ps1 += __shfl_xor_sync(0xffffffffu, ps1, 2);
        l0 = l0*s0f + ps0;
        l1 = l1*s1f + ps1;
#pragma unroll
        for (int df=0;df<16;df++){
            out[df][0]*=s0f; out[df][1]*=s0f; out[df][2]*=s1f; out[df][3]*=s1f;
        }

        // ---- PV: Phi*Vhi + Plo*Vhi + Phi*Vlo ----
#pragma unroll
        for (int kc=0;kc<4;kc++){
            unsigned ph[4], pl[4];
            hilo2(sc[2*kc][0],   sc[2*kc][1],   ph[0], pl[0]);
            hilo2(sc[2*kc][2],   sc[2*kc][3],   ph[1], pl[1]);
            hilo2(sc[2*kc+1][0], sc[2*kc+1][1], ph[2], pl[2]);
            hilo2(sc[2*kc+1][2], sc[2*kc+1][3], ph[3], pl[3]);
#pragma unroll
            for (int dt=0;dt<8;dt++){
                unsigned vo = (unsigned)(((kc*16+(lane&15))*136 + dt*16 + (lane>>4)*8)*2);
                unsigned v0,v1,v2,v3, u0,u1,u2,u3;
                ldsm4t(v0,v1,v2,v3, uVh+vo);
                ldsm4t(u0,u1,u2,u3, uVl+vo);
                mma16816(out[2*dt],   ph, v0,v1);
                mma16816(out[2*dt],   pl, v0,v1);
                mma16816(out[2*dt],   ph, u0,u1);
                mma16816(out[2*dt+1], ph, v2,v3);
                mma16816(out[2*dt+1], pl, v2,v3);
                mma16816(out[2*dt+1], ph, u2,u3);
            }
        }
    }

    // ---- epilogue: normalize, hi/lo split, write Wo B-pack [hi|hi|lo] ----
    float inv0 = 1.f/l0, inv1 = 1.f/l1;
    int qrow0 = qb + r0, qrow1 = qrow0 + 8;
#pragma unroll
    for (int df=0;df<16;df++){
        int colg = h*128 + df*8 + (lane&3)*2;
        unsigned hi, lo;
        hilo2(out[df][0]*inv0, out[df][1]*inv0, hi, lo);
        *(unsigned*)(attnT + (size_t)qrow0*K3_ + colg)        = hi;
        *(unsigned*)(attnT + (size_t)qrow0*K3_ + 2048 + colg) = hi;
        *(unsigned*)(attnT + (size_t)qrow0*K3_ + 4096 + colg) = lo;
        hilo2(out[df][2]*inv1, out[df][3]*inv1, hi, lo);
        *(unsigned*)(attnT + (size_t)qrow1*K3_ + colg)        = hi;
        *(unsigned*)(attnT + (size_t)qrow1*K3_ + 2048 + colg) = hi;
        *(unsigned*)(attnT + (size_t)qrow1*K3_ + 4096 + colg) = lo;
    }
}

// ---------------- launch ----------------
extern "C" void kernel_launch(void* const* d_in, const int* in_sizes, int n_in,
                              void* d_out, int out_size){
    const float* hidden = (const float*)d_in[0];
    const float* cosQD  = (const float*)d_in[1];
    const float* sinQD  = (const float*)d_in[2];
    const float* kcache = (const float*)d_in[6];
    const float* vcache = (const float*)d_in[7];
    const float* Wq = (const float*)d_in[8];
    const float* bq = (const float*)d_in[9];
    const float* Wk = (const float*)d_in[10];
    const float* bk = (const float*)d_in[11];
    const float* Wv = (const float*)d_in[12];
    const float* bv = (const float*)d_in[13];
    const float* Wo = (const float*)d_in[14];
    const int* cpos = (const int*)d_in[15];
    float* out = (float*)d_out;

    float *pq,*pk,*pv,*pkn,*pvn;
    bf16 *pqh,*pql,*pkh,*pkl,*pvh,*pvl,*pWq,*pWk,*pWv,*pWo,*pHid,*pAtt;
    cudaGetSymbolAddress((void**)&pq,g_q);     cudaGetSymbolAddress((void**)&pk,g_k);
    cudaGetSymbolAddress((void**)&pv,g_v);     cudaGetSymbolAddress((void**)&pkn,g_knew);
    cudaGetSymbolAddress((void**)&pvn,g_vnew);
    cudaGetSymbolAddress((void**)&pqh,g_qhi);  cudaGetSymbolAddress((void**)&pql,g_qlo);
    cudaGetSymbolAddress((void**)&pkh,g_khi);  cudaGetSymbolAddress((void**)&pkl,g_klo);
    cudaGetSymbolAddress((void**)&pvh,g_vhi);  cudaGetSymbolAddress((void**)&pvl,g_vlo);
    cudaGetSymbolAddress((void**)&pWq,g_WqPk); cudaGetSymbolAddress((void**)&pWk,g_WkPk);
    cudaGetSymbolAddress((void**)&pWv,g_WvPk); cudaGetSymbolAddress((void**)&pWo,g_WoPk);
    cudaGetSymbolAddress((void**)&pHid,g_hidT);cudaGetSymbolAddress((void**)&pAtt,g_attnT);

    // operand prep
    splitA_kernel<<<(HID_*HID_/4)/256, 256>>>(Wq, pWq, HID_*HID_/4);
    splitA_kernel<<<(KV_*D_*HID_/4)/256, 256>>>(Wk, pWk, KV_*D_*HID_/4);
    splitA_kernel<<<(KV_*D_*HID_/4)/256, 256>>>(Wv, pWv, KV_*D_*HID_/4);
    splitA_kernel<<<(HID_*HID_/4)/256, 256>>>(Wo, pWo, HID_*HID_/4);
    transpose_splitB_kernel<<<dim3(Q_/32, HID_/32), dim3(32,8)>>>(hidden, pHid);

    // projections (tensor-core, fp32 out)
    gemm_pk_kernel<<<dim3(8,16), 256>>>(pWq, pHid, bq, pq);
    gemm_pk_kernel<<<dim3(8, 8), 256>>>(pWk, pHid, bk, pk);
    gemm_pk_kernel<<<dim3(8, 8), 256>>>(pWv, pHid, bv, pv);

    // RoPE + transpose; Q folds 1/sqrt(D) and splits to bf16 hi/lo
    rope_q_split_kernel<<<dim3(Q_/32, H_), dim3(32,8)>>>(pq, cosQD, sinQD, pqh, pql, 0.08838834764831845f);
    rope_transpose_kernel<<<dim3(Q_/32, KV_), dim3(32,8)>>>(pk, cosQD, sinQD, pkn, 1);
    rope_transpose_kernel<<<dim3(Q_/32, KV_), dim3(32,8)>>>(pv, nullptr, nullptr, pvn, 0);

    // merged KV (cache + new) -> bf16 hi/lo
    merge_split_kv_kernel<<<(KV_*S_*D_/4)/256, 256>>>(kcache, vcache, pkn, pvn, cpos,
                                                      pkh, pkl, pvh, pvl);

    // flash attention
    const int ATTN_SMEM = 6*64*136*2;   // 104448 B
    cudaFuncSetAttribute(attn_kernel, cudaFuncAttributeMaxDynamicSharedMemorySize, ATTN_SMEM);
    attn_kernel<<<dim3(Q_/64, H_), 128, ATTN_SMEM>>>(pqh, pql, pkh, pkl, pvh, pvl, cpos, pAtt);

    // output projection (no bias)
    gemm_pk_kernel<<<dim3(8,16), 256>>>(pWo, pAtt, nullptr, out);
}

// round 8
// speedup vs baseline: 4.5373x; 1.6862x over previous
#include <cuda_runtime.h>
#include <cuda_bf16.h>
#include <cuda_fp16.h>
#include <math.h>

typedef __nv_bfloat16 bf16;
#define H_   16
#define KV_  8
#define D_   128
#define HID_ 2048
#define Q_   1024
#define S_   8192
#define K3_  6144

// ---------------- device-global scratch ----------------
__device__ float g_qkv[4096 * Q_];            // fused QKV projection [4096][1024] fp32
__device__ float g_knew[KV_*Q_*D_];
__device__ float g_vnew[KV_*Q_*D_];
__device__ __half g_qh [H_*Q_*D_];            // fp16 Q, RoPE'd, scaled
__device__ __half g_khf[KV_*S_*D_];           // fp16 merged K
__device__ __half g_vhf[KV_*S_*D_];           // fp16 merged V
__device__ bf16  g_Wqkv[(size_t)4096*K3_];    // A-pack [hi|lo|hi]
__device__ bf16  g_WoPk[(size_t)HID_*K3_];
__device__ bf16  g_hidT[(size_t)Q_*K3_];      // B-pack [hi|hi|lo]
__device__ bf16  g_attnT[(size_t)Q_*K3_];

// ---------------- PTX helpers ----------------
__device__ __forceinline__ void ldsm4(unsigned &r0,unsigned &r1,unsigned &r2,unsigned &r3,unsigned a){
    asm volatile("ldmatrix.sync.aligned.m8n8.x4.shared.b16 {%0,%1,%2,%3},[%4];"
                 :"=r"(r0),"=r"(r1),"=r"(r2),"=r"(r3):"r"(a));
}
__device__ __forceinline__ void ldsm4t(unsigned &r0,unsigned &r1,unsigned &r2,unsigned &r3,unsigned a){
    asm volatile("ldmatrix.sync.aligned.m8n8.x4.trans.shared.b16 {%0,%1,%2,%3},[%4];"
                 :"=r"(r0),"=r"(r1),"=r"(r2),"=r"(r3):"r"(a));
}
__device__ __forceinline__ void mma_bf16(float c[4], const unsigned a[4], unsigned b0, unsigned b1){
    asm volatile("mma.sync.aligned.m16n8k16.row.col.f32.bf16.bf16.f32 "
                 "{%0,%1,%2,%3},{%4,%5,%6,%7},{%8,%9},{%0,%1,%2,%3};"
                 :"+f"(c[0]),"+f"(c[1]),"+f"(c[2]),"+f"(c[3])
                 :"r"(a[0]),"r"(a[1]),"r"(a[2]),"r"(a[3]),"r"(b0),"r"(b1));
}
__device__ __forceinline__ void mma_f16(float c[4], const unsigned a[4], unsigned b0, unsigned b1){
    asm volatile("mma.sync.aligned.m16n8k16.row.col.f32.f16.f16.f32 "
                 "{%0,%1,%2,%3},{%4,%5,%6,%7},{%8,%9},{%0,%1,%2,%3};"
                 :"+f"(c[0]),"+f"(c[1]),"+f"(c[2]),"+f"(c[3])
                 :"r"(a[0]),"r"(a[1]),"r"(a[2]),"r"(a[3]),"r"(b0),"r"(b1));
}
__device__ __forceinline__ void cpa16(unsigned s, const void* g){
    asm volatile("cp.async.cg.shared.global [%0],[%1],16;"::"r"(s),"l"(g));
}
#define CPC()  asm volatile("cp.async.commit_group;")
#define CPW0() asm volatile("cp.async.wait_group 0;")
#define CPW1() asm volatile("cp.async.wait_group 1;")

__device__ __forceinline__ void hilo2(float x, float y, unsigned &hi, unsigned &lo){
    bf16 hx=__float2bfloat16_rn(x), hy=__float2bfloat16_rn(y);
    __nv_bfloat162 hp=__halves2bfloat162(hx,hy); hi=*reinterpret_cast<unsigned*>(&hp);
    bf16 lx=__float2bfloat16_rn(x-__bfloat162float(hx));
    bf16 ly=__float2bfloat16_rn(y-__bfloat162float(hy));
    __nv_bfloat162 lp=__halves2bfloat162(lx,ly); lo=*reinterpret_cast<unsigned*>(&lp);
}
__device__ __forceinline__ unsigned f2h2(float x, float y){
    __half2 h = __floats2half2_rn(x,y); return *reinterpret_cast<unsigned*>(&h);
}

// ---------------- prep: weight A-pack [hi|lo|hi] ----------------
__global__ __launch_bounds__(256)
void splitA_kernel(const float* __restrict__ W, bf16* __restrict__ dst, int total4){
    int idx = blockIdx.x*256 + threadIdx.x;
    if (idx >= total4) return;
    size_t lin = (size_t)idx*4;
    int col = (int)(lin & (HID_-1));
    size_t row = lin >> 11;
    float4 w = *(const float4*)(W + lin);
    unsigned h0,l0,h1,l1;
    hilo2(w.x,w.y,h0,l0); hilo2(w.z,w.w,h1,l1);
    size_t b = row*K3_ + col;
    *(uint2*)(dst+b)        = make_uint2(h0,h1);
    *(uint2*)(dst+b+HID_)   = make_uint2(l0,l1);
    *(uint2*)(dst+b+2*HID_) = make_uint2(h0,h1);
}

// ---------------- prep: hidden -> hidT B-pack [hi|hi|lo] ----------------
__global__ __launch_bounds__(256)
void transpose_splitB_kernel(const float* __restrict__ src, bf16* __restrict__ dst){
    __shared__ float t[32][33];
    const int tx=threadIdx.x, ty=threadIdx.y;          // 32 x 8
    const int n0=blockIdx.x*32, k0=blockIdx.y*32;
#pragma unroll
    for (int r=0;r<4;r++)
        t[ty+8*r][tx] = src[(size_t)(k0+ty+8*r)*Q_ + n0+tx];
    __syncthreads();
#pragma unroll
    for (int r=0;r<4;r++){
        int n = ty+8*r;
        float v = t[tx][n];
        bf16 hb = __float2bfloat16_rn(v);
        bf16 lb = __float2bfloat16_rn(v - __bfloat162float(hb));
        size_t b = (size_t)(n0+n)*K3_ + k0+tx;
        dst[b]=hb; dst[b+HID_]=hb; dst[b+2*HID_]=lb;
    }
}

// ---------------- packed-K bf16 GEMM: C[M][1024] = A[M][6144] * B[1024][6144]^T (+bias) ----------------
// 128x128 CTA tile, 8 warps of 32x64, k-step 32, cp.async double buffer, stride-40 smem.
// Bias selected per output row: [0,2048)->b0, [2048,3072)->b1, [3072,4096)->b2.
__global__ __launch_bounds__(256)
void gemm_pk_kernel(const bf16* __restrict__ A, const bf16* __restrict__ B,
                    const float* __restrict__ b0, const float* __restrict__ b1,
                    const float* __restrict__ b2, float* __restrict__ C){
    __shared__ bf16 sA[2][128*40];
    __shared__ bf16 sB[2][128*40];
    const int tid=threadIdx.x, lane=tid&31, warp=tid>>5;
    const int wm = warp>>1, wn = warp&1;
    const int m0 = blockIdx.y*128, n0 = blockIdx.x*128;
    const unsigned uA=(unsigned)__cvta_generic_to_shared(&sA[0][0]);
    const unsigned uB=(unsigned)__cvta_generic_to_shared(&sB[0][0]);

    float acc[2][8][4];
#pragma unroll
    for (int a=0;a<2;a++)
#pragma unroll
        for (int b=0;b<8;b++)
#pragma unroll
            for (int c=0;c<4;c++) acc[a][b][c]=0.f;

    auto load=[&](int st,int k0){
#pragma unroll
        for (int i=0;i<2;i++){
            int c = tid + i*256;
            int row = c>>2, seg = c&3;
            cpa16(uA + (st*5120 + row*40 + seg*8)*2, A + (size_t)(m0+row)*K3_ + k0 + seg*8);
            cpa16(uB + (st*5120 + row*40 + seg*8)*2, B + (size_t)(n0+row)*K3_ + k0 + seg*8);
        }
    };
    load(0,0); CPC();

    for (int kt=0;kt<192;kt++){
        int st = kt&1;
        if (kt<191){ load(st^1,(kt+1)*32); CPC(); CPW1(); } else { CPW0(); }
        __syncthreads();
#pragma unroll
        for (int kh=0;kh<2;kh++){
            unsigned a0[4], a1[4];
            unsigned ao = (unsigned)((st*5120 + (wm*32+(lane&15))*40 + kh*16 + (lane>>4)*8)*2);
            ldsm4(a0[0],a0[1],a0[2],a0[3], uA+ao);
            ldsm4(a1[0],a1[1],a1[2],a1[3], uA+ao + 16*40*2);
            unsigned bf_[8][2];
#pragma unroll
            for (int nt=0;nt<4;nt++){
                unsigned bo = (unsigned)((st*5120 + (wn*64+nt*16+(lane&15))*40 + kh*16 + (lane>>4)*8)*2);
                unsigned r0,r1,r2,r3;
                ldsm4(r0,r1,r2,r3, uB+bo);
                bf_[2*nt][0]=r0; bf_[2*nt][1]=r2; bf_[2*nt+1][0]=r1; bf_[2*nt+1][1]=r3;
            }
#pragma unroll
            for (int nf=0;nf<8;nf++){
                mma_bf16(acc[0][nf], a0, bf_[nf][0], bf_[nf][1]);
                mma_bf16(acc[1][nf], a1, bf_[nf][0], bf_[nf][1]);
            }
        }
        __syncthreads();
    }
#pragma unroll
    for (int mf=0;mf<2;mf++)
#pragma unroll
        for (int nf=0;nf<8;nf++){
            int row = m0 + wm*32 + mf*16 + (lane>>2);
            int col = n0 + wn*64 + nf*8 + (lane&3)*2;
            float bva = 0.f, bvb = 0.f;
            if (b0){
                int r2 = row + 8;
                bva = (row<2048)? b0[row] : ((row<3072)? b1[row-2048] : b2[row-3072]);
                bvb = (r2 <2048)? b0[r2]  : ((r2 <3072)? b1[r2 -2048] : b2[r2 -3072]);
            }
            C[(size_t)row*Q_ + col]       = acc[mf][nf][0] + bva;
            C[(size_t)row*Q_ + col + 1]   = acc[mf][nf][1] + bva;
            C[(size_t)(row+8)*Q_ + col]   = acc[mf][nf][2] + bvb;
            C[(size_t)(row+8)*Q_ + col+1] = acc[mf][nf][3] + bvb;
        }
}

// ---------------- RoPE + transpose (fp32 out) for new K/V ----------------
__global__ __launch_bounds__(256)
void rope_transpose_kernel(const float* __restrict__ src, const float* __restrict__ cosQD,
                           const float* __restrict__ sinQD, float* __restrict__ dst, int do_rope){
    __shared__ float tile[128][33];
    const int tx=threadIdx.x, ty=threadIdx.y;
    const int i0=blockIdx.x*32, h=blockIdx.y;
#pragma unroll
    for (int r=0;r<16;r++)
        tile[r*8+ty][tx] = src[(size_t)(h*128 + r*8+ty)*Q_ + i0+tx];
    __syncthreads();
    const int t = ty*32+tx;
#pragma unroll
    for (int r=0;r<16;r++){
        int idx = r*256 + t;
        int d = idx & 127, i = idx >> 7;
        float v = tile[d][i], out;
        if (do_rope){
            float o = (d<64) ? -tile[d+64][i] : tile[d-64][i];
            out = v*cosQD[(size_t)(i0+i)*128+d] + o*sinQD[(size_t)(i0+i)*128+d];
        } else out = v;
        dst[(size_t)(h*Q_ + i0+i)*128 + d] = out;
    }
}

// ---------------- RoPE + transpose + fp16 for Q (folds 1/sqrt(D)) ----------------
__global__ __launch_bounds__(256)
void rope_q_fp16_kernel(const float* __restrict__ src, const float* __restrict__ cosQD,
                        const float* __restrict__ sinQD, __half* __restrict__ qh, float scale){
    __shared__ float tile[128][33];
    const int tx=threadIdx.x, ty=threadIdx.y;
    const int i0=blockIdx.x*32, h=blockIdx.y;
#pragma unroll
    for (int r=0;r<16;r++)
        tile[r*8+ty][tx] = src[(size_t)(h*128 + r*8+ty)*Q_ + i0+tx];
    __syncthreads();
    const int t = ty*32+tx;
#pragma unroll
    for (int r=0;r<16;r++){
        int idx = r*256 + t;
        int d = idx & 127, i = idx >> 7;
        float v = tile[d][i];
        float o = (d<64) ? -tile[d+64][i] : tile[d-64][i];
        float out = (v*cosQD[(size_t)(i0+i)*128+d] + o*sinQD[(size_t)(i0+i)*128+d])*scale;
        qh[((size_t)h*Q_ + i0+i)*128 + d] = __float2half_rn(out);
    }
}

// ---------------- merged KV cache -> fp16 [kv][S][D] ----------------
__global__ __launch_bounds__(256)
void merge_kv_fp16_kernel(const float* __restrict__ kc_, const float* __restrict__ vc_,
                          const float* __restrict__ kn, const float* __restrict__ vn,
                          const int* __restrict__ cposp,
                          __half* __restrict__ khf, __half* __restrict__ vhf){
    int idx = blockIdx.x*256 + threadIdx.x;
    const int total = KV_*S_*D_/4;
    if (idx >= total) return;
    int cpos = cposp[0];
    size_t lin = (size_t)idx*4;
    int s  = (int)((lin>>7) & (S_-1));
    int kv = (int)(lin>>20);
    int d  = (int)(lin & 127);
    bool nw = (s >= cpos) && (s < cpos + Q_);
    size_t nlin = ((size_t)kv*Q_ + (s-cpos))*128 + d;
    float4 k4 = nw ? *(const float4*)(kn+nlin) : *(const float4*)(kc_+lin);
    float4 v4 = nw ? *(const float4*)(vn+nlin) : *(const float4*)(vc_+lin);
    *(uint2*)(khf+lin) = make_uint2(f2h2(k4.x,k4.y), f2h2(k4.z,k4.w));
    *(uint2*)(vhf+lin) = make_uint2(f2h2(v4.x,v4.y), f2h2(v4.z,v4.w));
}

// ---------------- flash attention, fp16 single-pass MMA ----------------
// BQ=64 (4 warps x 16 exclusive rows), BS=64. Epilogue writes bf16 [hi|hi|lo] pack.
__global__ __launch_bounds__(128)
void attn_kernel(const __half* __restrict__ qh, const __half* __restrict__ khf,
                 const __half* __restrict__ vhf, const int* __restrict__ cposp,
                 bf16* __restrict__ attnT){
    extern __shared__ __half smh[];
    const int TS = 64*136;
    const int tid=threadIdx.x, lane=tid&31, w=tid>>5;
    const int q0=blockIdx.x*64, h=blockIdx.y, kv=h>>1;
    const int cpos = cposp[0];
    const unsigned sb=(unsigned)__cvta_generic_to_shared(smh);
    const unsigned uQ=sb, uK=sb+TS*2, uV=sb+2*TS*2;

#pragma unroll
    for (int i=0;i<8;i++){
        int c = tid + i*128;
        int row = c>>4, seg = c&15;
        cpa16(uQ + (unsigned)((row*136 + seg*8)*2),
              qh + ((size_t)h*Q_ + q0 + row)*128 + seg*8);
    }
    CPC(); CPW0(); __syncthreads();

    float out[16][4];
#pragma unroll
    for (int a=0;a<16;a++)
#pragma unroll
        for (int c=0;c<4;c++) out[a][c]=0.f;
    float m0=-1e30f, m1=-1e30f, l0=0.f, l1=0.f;
    const int r0 = lane>>2, qb = q0 + w*16;

    int nblk = (cpos + q0 + 63)/64 + 1;
    if (nblk > S_/64) nblk = S_/64;

    for (int sbk=0; sbk<nblk; sbk++){
        const int s0 = sbk*64;
        __syncthreads();
#pragma unroll
        for (int i=0;i<8;i++){
            int c = tid + i*128;
            int row = c>>4, seg = c&15;
            size_t gk = ((size_t)kv*S_ + s0 + row)*128 + seg*8;
            unsigned so = (unsigned)((row*136 + seg*8)*2);
            cpa16(uK+so, khf+gk);
            cpa16(uV+so, vhf+gk);
        }
        CPC(); CPW0(); __syncthreads();

        // ---- scores ----
        float sc[8][4];
#pragma unroll
        for (int a=0;a<8;a++)
#pragma unroll
            for (int c=0;c<4;c++) sc[a][c]=0.f;
#pragma unroll
        for (int kd=0;kd<8;kd++){
            unsigned aq[4];
            unsigned qo = (unsigned)(((w*16+(lane&15))*136 + kd*16 + (lane>>4)*8)*2);
            ldsm4(aq[0],aq[1],aq[2],aq[3], uQ+qo);
#pragma unroll
            for (int nt=0;nt<4;nt++){
                unsigned ko = (unsigned)(((nt*16+(lane&15))*136 + kd*16 + (lane>>4)*8)*2);
                unsigned k0r,k1r,k2r,k3r;
                ldsm4(k0r,k1r,k2r,k3r, uK+ko);
                mma_f16(sc[2*nt],   aq, k0r,k2r);
                mma_f16(sc[2*nt+1], aq, k1r,k3r);
            }
        }

        // ---- causal mask ----
        if (s0 + 63 > cpos + qb){
            int lim0 = cpos + qb + r0, lim1 = lim0 + 8;
#pragma unroll
            for (int nf=0;nf<8;nf++){
                int j = s0 + nf*8 + 2*(lane&3);
                if (j   > lim0) sc[nf][0] = -1e30f;
                if (j+1 > lim0) sc[nf][1] = -1e30f;
                if (j   > lim1) sc[nf][2] = -1e30f;
                if (j+1 > lim1) sc[nf][3] = -1e30f;
            }
        }

        // ---- online softmax ----
        float mx0=-1e30f, mx1=-1e30f;
#pragma unroll
        for (int nf=0;nf<8;nf++){
            mx0 = fmaxf(mx0, fmaxf(sc[nf][0], sc[nf][1]));
            mx1 = fmaxf(mx1, fmaxf(sc[nf][2], sc[nf][3]));
        }
        mx0 = fmaxf(mx0, __shfl_xor_sync(0xffffffffu, mx0, 1));
        mx0 = fmaxf(mx0, __shfl_xor_sync(0xffffffffu, mx0, 2));
        mx1 = fmaxf(mx1, __shfl_xor_sync(0xffffffffu, mx1, 1));
        mx1 = fmaxf(mx1, __shfl_xor_sync(0xffffffffu, mx1, 2));
        float n0_ = fmaxf(m0, mx0), n1_ = fmaxf(m1, mx1);
        float s0f = __expf(m0 - n0_), s1f = __expf(m1 - n1_);
        m0 = n0_; m1 = n1_;
        float ps0=0.f, ps1=0.f;
#pragma unroll
        for (int nf=0;nf<8;nf++){
            sc[nf][0]=__expf(sc[nf][0]-m0); ps0+=sc[nf][0];
            sc[nf][1]=__expf(sc[nf][1]-m0); ps0+=sc[nf][1];
            sc[nf][2]=__expf(sc[nf][2]-m1); ps1+=sc[nf][2];
            sc[nf][3]=__expf(sc[nf][3]-m1); ps1+=sc[nf][3];
        }
        ps0 += __shfl_xor_sync(0xffffffffu, ps0, 1);
        ps0 += __shfl_xor_sync(0xffffffffu, ps0, 2);
        ps1 += __shfl_xor_sync(0xffffffffu, ps1, 1);
        ps1 += __shfl_xor_sync(0xffffffffu, ps1, 2);
        l0 = l0*s0f + ps0;
        l1 = l1*s1f + ps1;
#pragma unroll
        for (int df=0;df<16;df++){
            out[df][0]*=s0f; out[df][1]*=s0f; out[df][2]*=s1f; out[df][3]*=s1f;
        }

        // ---- PV ----
#pragma unroll
        for (int kc=0;kc<4;kc++){
            unsigned ph[4];
            ph[0] = f2h2(sc[2*kc][0],   sc[2*kc][1]);
            ph[1] = f2h2(sc[2*kc][2],   sc[2*kc][3]);
            ph[2] = f2h2(sc[2*kc+1][0], sc[2*kc+1][1]);
            ph[3] = f2h2(sc[2*kc+1][2], sc[2*kc+1][3]);
#pragma unroll
            for (int dt=0;dt<8;dt++){
                unsigned vo = (unsigned)(((kc*16+(lane&15))*136 + dt*16 + (lane>>4)*8)*2);
                unsigned v0,v1,v2,v3;
                ldsm4t(v0,v1,v2,v3, uV+vo);
                mma_f16(out[2*dt],   ph, v0,v1);
                mma_f16(out[2*dt+1], ph, v2,v3);
            }
        }
    }

    // ---- epilogue: normalize, bf16 hi/lo split, write Wo B-pack [hi|hi|lo] ----
    float inv0 = 1.f/l0, inv1 = 1.f/l1;
    int qrow0 = qb + r0, qrow1 = qrow0 + 8;
#pragma unroll
    for (int df=0;df<16;df++){
        int colg = h*128 + df*8 + (lane&3)*2;
        unsigned hi, lo;
        hilo2(out[df][0]*inv0, out[df][1]*inv0, hi, lo);
        *(unsigned*)(attnT + (size_t)qrow0*K3_ + colg)        = hi;
        *(unsigned*)(attnT + (size_t)qrow0*K3_ + 2048 + colg) = hi;
        *(unsigned*)(attnT + (size_t)qrow0*K3_ + 4096 + colg) = lo;
        hilo2(out[df][2]*inv1, out[df][3]*inv1, hi, lo);
        *(unsigned*)(attnT + (size_t)qrow1*K3_ + colg)        = hi;
        *(unsigned*)(attnT + (size_t)qrow1*K3_ + 2048 + colg) = hi;
        *(unsigned*)(attnT + (size_t)qrow1*K3_ + 4096 + colg) = lo;
    }
}

// ---------------- launch ----------------
extern "C" void kernel_launch(void* const* d_in, const int* in_sizes, int n_in,
                              void* d_out, int out_size){
    const float* hidden = (const float*)d_in[0];
    const float* cosQD  = (const float*)d_in[1];
    const float* sinQD  = (const float*)d_in[2];
    const float* kcache = (const float*)d_in[6];
    const float* vcache = (const float*)d_in[7];
    const float* Wq = (const float*)d_in[8];
    const float* bq = (const float*)d_in[9];
    const float* Wk = (const float*)d_in[10];
    const float* bk = (const float*)d_in[11];
    const float* Wv = (const float*)d_in[12];
    const float* bv = (const float*)d_in[13];
    const float* Wo = (const float*)d_in[14];
    const int* cpos = (const int*)d_in[15];
    float* out = (float*)d_out;

    float *pqkv,*pkn,*pvn;
    __half *pqh,*pkhf,*pvhf;
    bf16 *pWqkv,*pWo,*pHid,*pAtt;
    cudaGetSymbolAddress((void**)&pqkv,g_qkv);
    cudaGetSymbolAddress((void**)&pkn,g_knew);  cudaGetSymbolAddress((void**)&pvn,g_vnew);
    cudaGetSymbolAddress((void**)&pqh,g_qh);
    cudaGetSymbolAddress((void**)&pkhf,g_khf);  cudaGetSymbolAddress((void**)&pvhf,g_vhf);
    cudaGetSymbolAddress((void**)&pWqkv,g_Wqkv);cudaGetSymbolAddress((void**)&pWo,g_WoPk);
    cudaGetSymbolAddress((void**)&pHid,g_hidT); cudaGetSymbolAddress((void**)&pAtt,g_attnT);

    // operand prep (fused QKV weight pack at row offsets 0 / 2048 / 3072)
    splitA_kernel<<<(HID_*HID_/4)/256, 256>>>(Wq, pWqkv, HID_*HID_/4);
    splitA_kernel<<<(KV_*D_*HID_/4)/256, 256>>>(Wk, pWqkv + (size_t)2048*K3_, KV_*D_*HID_/4);
    splitA_kernel<<<(KV_*D_*HID_/4)/256, 256>>>(Wv, pWqkv + (size_t)3072*K3_, KV_*D_*HID_/4);
    splitA_kernel<<<(HID_*HID_/4)/256, 256>>>(Wo, pWo, HID_*HID_/4);
    transpose_splitB_kernel<<<dim3(Q_/32, HID_/32), dim3(32,8)>>>(hidden, pHid);

    // fused QKV projection (M=4096) on HMMA
    gemm_pk_kernel<<<dim3(8,32), 256>>>(pWqkv, pHid, bq, bk, bv, pqkv);

    // RoPE (+fp16 for Q, folding 1/sqrt(D))
    rope_q_fp16_kernel<<<dim3(Q_/32, H_), dim3(32,8)>>>(pqkv, cosQD, sinQD, pqh, 0.08838834764831845f);
    rope_transpose_kernel<<<dim3(Q_/32, KV_), dim3(32,8)>>>(pqkv + (size_t)2048*Q_, cosQD, sinQD, pkn, 1);
    rope_transpose_kernel<<<dim3(Q_/32, KV_), dim3(32,8)>>>(pqkv + (size_t)3072*Q_, nullptr, nullptr, pvn, 0);

    // merged KV -> fp16
    merge_kv_fp16_kernel<<<(KV_*S_*D_/4)/256, 256>>>(kcache, vcache, pkn, pvn, cpos, pkhf, pvhf);

    // flash attention (fp16 single-pass)
    const int ATTN_SMEM = 3*64*136*2;   // 52224 B
    cudaFuncSetAttribute(attn_kernel, cudaFuncAttributeMaxDynamicSharedMemorySize, ATTN_SMEM);
    attn_kernel<<<dim3(Q_/64, H_), 128, ATTN_SMEM>>>(pqh, pkhf, pvhf, cpos, pAtt);

    // output projection on HMMA (no bias)
    gemm_pk_kernel<<<dim3(8,16), 256>>>(pWo, pAtt, nullptr, nullptr, nullptr, out);
}

// round 9
// speedup vs baseline: 5.8111x; 1.2807x over previous
#include <cuda_runtime.h>
#include <cuda_bf16.h>
#include <cuda_fp16.h>
#include <math.h>

#define H_   16
#define KV_  8
#define D_   128
#define HID_ 2048
#define Q_   1024
#define S_   8192
#define K2_  4096

// ---------------- device-global scratch ----------------
__device__ float  g_qkv[4096 * Q_];            // fused QKV projection [4096][1024] fp32
__device__ float  g_knew[KV_*Q_*D_];
__device__ float  g_vnew[KV_*Q_*D_];
__device__ __half g_qh [H_*Q_*D_];             // fp16 Q, RoPE'd, scaled
__device__ __half g_khf[KV_*S_*D_];            // fp16 merged K
__device__ __half g_vhf[KV_*S_*D_];            // fp16 merged V
__device__ __half g_Wqkv[(size_t)4096*K2_];    // A-pack [ah|al] of 64*W
__device__ __half g_WoPk[(size_t)HID_*K2_];
__device__ __half g_hidT[(size_t)Q_*K2_];      // B-pack [bh|bh]
__device__ __half g_attnT[(size_t)Q_*K2_];     // B-pack [bh|bh]

// ---------------- PTX helpers ----------------
__device__ __forceinline__ void ldsm4(unsigned &r0,unsigned &r1,unsigned &r2,unsigned &r3,unsigned a){
    asm volatile("ldmatrix.sync.aligned.m8n8.x4.shared.b16 {%0,%1,%2,%3},[%4];"
                 :"=r"(r0),"=r"(r1),"=r"(r2),"=r"(r3):"r"(a));
}
__device__ __forceinline__ void ldsm4t(unsigned &r0,unsigned &r1,unsigned &r2,unsigned &r3,unsigned a){
    asm volatile("ldmatrix.sync.aligned.m8n8.x4.trans.shared.b16 {%0,%1,%2,%3},[%4];"
                 :"=r"(r0),"=r"(r1),"=r"(r2),"=r"(r3):"r"(a));
}
__device__ __forceinline__ void mma_f16(float c[4], const unsigned a[4], unsigned b0, unsigned b1){
    asm volatile("mma.sync.aligned.m16n8k16.row.col.f32.f16.f16.f32 "
                 "{%0,%1,%2,%3},{%4,%5,%6,%7},{%8,%9},{%0,%1,%2,%3};"
                 :"+f"(c[0]),"+f"(c[1]),"+f"(c[2]),"+f"(c[3])
                 :"r"(a[0]),"r"(a[1]),"r"(a[2]),"r"(a[3]),"r"(b0),"r"(b1));
}
__device__ __forceinline__ void cpa16(unsigned s, const void* g){
    asm volatile("cp.async.cg.shared.global [%0],[%1],16;"::"r"(s),"l"(g));
}
#define CPC()  asm volatile("cp.async.commit_group;")
#define CPW0() asm volatile("cp.async.wait_group 0;")
#define CPW1() asm volatile("cp.async.wait_group 1;")

__device__ __forceinline__ unsigned f2h2(float x, float y){
    __half2 h = __floats2half2_rn(x,y); return *reinterpret_cast<unsigned*>(&h);
}
// fp16 hi/lo split of a pair
__device__ __forceinline__ void hilo2h(float x, float y, unsigned &hi, unsigned &lo){
    __half hx=__float2half_rn(x), hy=__float2half_rn(y);
    __half2 hp=__halves2half2(hx,hy); hi=*reinterpret_cast<unsigned*>(&hp);
    __half lx=__float2half_rn(x-__half2float(hx));
    __half ly=__float2half_rn(y-__half2float(hy));
    __half2 lp=__halves2half2(lx,ly); lo=*reinterpret_cast<unsigned*>(&lp);
}

// ---------------- prep: weight A-pack [ah|al] of 64*W ----------------
__global__ __launch_bounds__(256)
void splitA_kernel(const float* __restrict__ W, __half* __restrict__ dst, int total4){
    int idx = blockIdx.x*256 + threadIdx.x;
    if (idx >= total4) return;
    size_t lin = (size_t)idx*4;
    int col = (int)(lin & (HID_-1));
    size_t row = lin >> 11;
    float4 w = *(const float4*)(W + lin);
    unsigned h0,l0,h1,l1;
    hilo2h(w.x*64.f, w.y*64.f, h0, l0);
    hilo2h(w.z*64.f, w.w*64.f, h1, l1);
    size_t b = row*K2_ + col;
    *(uint2*)(dst+b)        = make_uint2(h0,h1);
    *(uint2*)(dst+b+HID_)   = make_uint2(l0,l1);
}

// ---------------- prep: hidden [2048][1024] -> hidT B-pack [bh|bh] ----------------
__global__ __launch_bounds__(256)
void transpose_splitB_kernel(const float* __restrict__ src, __half* __restrict__ dst){
    __shared__ float t[32][33];
    const int tx=threadIdx.x, ty=threadIdx.y;          // 32 x 8
    const int n0=blockIdx.x*32, k0=blockIdx.y*32;
#pragma unroll
    for (int r=0;r<4;r++)
        t[ty+8*r][tx] = src[(size_t)(k0+ty+8*r)*Q_ + n0+tx];
    __syncthreads();
#pragma unroll
    for (int r=0;r<4;r++){
        int n = ty+8*r;
        __half hb = __float2half_rn(t[tx][n]);
        size_t b = (size_t)(n0+n)*K2_ + k0+tx;
        dst[b]=hb; dst[b+HID_]=hb;
    }
}

// ---------------- packed-K fp16 GEMM: C[M][1024] = (A/64)[M][4096]*B[1024][4096]^T (+bias) ----------------
// 128x128 CTA tile, 8 warps of 32x64, k-step 32, cp.async double buffer, stride-40 smem.
__global__ __launch_bounds__(256)
void gemm_pk_kernel(const __half* __restrict__ A, const __half* __restrict__ B,
                    const float* __restrict__ b0, const float* __restrict__ b1,
                    const float* __restrict__ b2, float* __restrict__ C){
    __shared__ __half sA[2][128*40];
    __shared__ __half sB[2][128*40];
    const int tid=threadIdx.x, lane=tid&31, warp=tid>>5;
    const int wm = warp>>1, wn = warp&1;
    const int m0 = blockIdx.y*128, n0 = blockIdx.x*128;
    const unsigned uA=(unsigned)__cvta_generic_to_shared(&sA[0][0]);
    const unsigned uB=(unsigned)__cvta_generic_to_shared(&sB[0][0]);

    float acc[2][8][4];
#pragma unroll
    for (int a=0;a<2;a++)
#pragma unroll
        for (int b=0;b<8;b++)
#pragma unroll
            for (int c=0;c<4;c++) acc[a][b][c]=0.f;

    auto load=[&](int st,int k0){
#pragma unroll
        for (int i=0;i<2;i++){
            int c = tid + i*256;
            int row = c>>2, seg = c&3;
            cpa16(uA + (st*5120 + row*40 + seg*8)*2, A + (size_t)(m0+row)*K2_ + k0 + seg*8);
            cpa16(uB + (st*5120 + row*40 + seg*8)*2, B + (size_t)(n0+row)*K2_ + k0 + seg*8);
        }
    };
    load(0,0); CPC();

    for (int kt=0;kt<128;kt++){
        int st = kt&1;
        if (kt<127){ load(st^1,(kt+1)*32); CPC(); CPW1(); } else { CPW0(); }
        __syncthreads();
#pragma unroll
        for (int kh=0;kh<2;kh++){
            unsigned a0[4], a1[4];
            unsigned ao = (unsigned)((st*5120 + (wm*32+(lane&15))*40 + kh*16 + (lane>>4)*8)*2);
            ldsm4(a0[0],a0[1],a0[2],a0[3], uA+ao);
            ldsm4(a1[0],a1[1],a1[2],a1[3], uA+ao + 16*40*2);
            unsigned bf_[8][2];
#pragma unroll
            for (int nt=0;nt<4;nt++){
                unsigned bo = (unsigned)((st*5120 + (wn*64+nt*16+(lane&15))*40 + kh*16 + (lane>>4)*8)*2);
                unsigned r0,r1,r2,r3;
                ldsm4(r0,r1,r2,r3, uB+bo);
                bf_[2*nt][0]=r0; bf_[2*nt][1]=r2; bf_[2*nt+1][0]=r1; bf_[2*nt+1][1]=r3;
            }
#pragma unroll
            for (int nf=0;nf<8;nf++){
                mma_f16(acc[0][nf], a0, bf_[nf][0], bf_[nf][1]);
                mma_f16(acc[1][nf], a1, bf_[nf][0], bf_[nf][1]);
            }
        }
        __syncthreads();
    }
    const float SC = 0.015625f;   // 1/64 (undo A scaling)
#pragma unroll
    for (int mf=0;mf<2;mf++)
#pragma unroll
        for (int nf=0;nf<8;nf++){
            int row = m0 + wm*32 + mf*16 + (lane>>2);
            int col = n0 + wn*64 + nf*8 + (lane&3)*2;
            float bva = 0.f, bvb = 0.f;
            if (b0){
                int r2 = row + 8;
                bva = (row<2048)? b0[row] : ((row<3072)? b1[row-2048] : b2[row-3072]);
                bvb = (r2 <2048)? b0[r2]  : ((r2 <3072)? b1[r2 -2048] : b2[r2 -3072]);
            }
            C[(size_t)row*Q_ + col]       = acc[mf][nf][0]*SC + bva;
            C[(size_t)row*Q_ + col + 1]   = acc[mf][nf][1]*SC + bva;
            C[(size_t)(row+8)*Q_ + col]   = acc[mf][nf][2]*SC + bvb;
            C[(size_t)(row+8)*Q_ + col+1] = acc[mf][nf][3]*SC + bvb;
        }
}

// ---------------- RoPE + transpose (fp32 out) for new K/V ----------------
__global__ __launch_bounds__(256)
void rope_transpose_kernel(const float* __restrict__ src, const float* __restrict__ cosQD,
                           const float* __restrict__ sinQD, float* __restrict__ dst, int do_rope){
    __shared__ float tile[128][33];
    const int tx=threadIdx.x, ty=threadIdx.y;
    const int i0=blockIdx.x*32, h=blockIdx.y;
#pragma unroll
    for (int r=0;r<16;r++)
        tile[r*8+ty][tx] = src[(size_t)(h*128 + r*8+ty)*Q_ + i0+tx];
    __syncthreads();
    const int t = ty*32+tx;
#pragma unroll
    for (int r=0;r<16;r++){
        int idx = r*256 + t;
        int d = idx & 127, i = idx >> 7;
        float v = tile[d][i], out;
        if (do_rope){
            float o = (d<64) ? -tile[d+64][i] : tile[d-64][i];
            out = v*cosQD[(size_t)(i0+i)*128+d] + o*sinQD[(size_t)(i0+i)*128+d];
        } else out = v;
        dst[(size_t)(h*Q_ + i0+i)*128 + d] = out;
    }
}

// ---------------- RoPE + transpose + fp16 for Q (folds 1/sqrt(D)) ----------------
__global__ __launch_bounds__(256)
void rope_q_fp16_kernel(const float* __restrict__ src, const float* __restrict__ cosQD,
                        const float* __restrict__ sinQD, __half* __restrict__ qh, float scale){
    __shared__ float tile[128][33];
    const int tx=threadIdx.x, ty=threadIdx.y;
    const int i0=blockIdx.x*32, h=blockIdx.y;
#pragma unroll
    for (int r=0;r<16;r++)
        tile[r*8+ty][tx] = src[(size_t)(h*128 + r*8+ty)*Q_ + i0+tx];
    __syncthreads();
    const int t = ty*32+tx;
#pragma unroll
    for (int r=0;r<16;r++){
        int idx = r*256 + t;
        int d = idx & 127, i = idx >> 7;
        float v = tile[d][i];
        float o = (d<64) ? -tile[d+64][i] : tile[d-64][i];
        float out = (v*cosQD[(size_t)(i0+i)*128+d] + o*sinQD[(size_t)(i0+i)*128+d])*scale;
        qh[((size_t)h*Q_ + i0+i)*128 + d] = __float2half_rn(out);
    }
}

// ---------------- merged KV cache -> fp16 [kv][S][D] ----------------
__global__ __launch_bounds__(256)
void merge_kv_fp16_kernel(const float* __restrict__ kc_, const float* __restrict__ vc_,
                          const float* __restrict__ kn, const float* __restrict__ vn,
                          const int* __restrict__ cposp,
                          __half* __restrict__ khf, __half* __restrict__ vhf){
    int idx = blockIdx.x*256 + threadIdx.x;
    const int total = KV_*S_*D_/4;
    if (idx >= total) return;
    int cpos = cposp[0];
    size_t lin = (size_t)idx*4;
    int s  = (int)((lin>>7) & (S_-1));
    int kv = (int)(lin>>20);
    int d  = (int)(lin & 127);
    bool nw = (s >= cpos) && (s < cpos + Q_);
    size_t nlin = ((size_t)kv*Q_ + (s-cpos))*128 + d;
    float4 k4 = nw ? *(const float4*)(kn+nlin) : *(const float4*)(kc_+lin);
    float4 v4 = nw ? *(const float4*)(vn+nlin) : *(const float4*)(vc_+lin);
    *(uint2*)(khf+lin) = make_uint2(f2h2(k4.x,k4.y), f2h2(k4.z,k4.w));
    *(uint2*)(vhf+lin) = make_uint2(f2h2(v4.x,v4.y), f2h2(v4.z,v4.w));
}

// ---------------- flash attention, fp16 MMA, double-buffered K/V ----------------
// BQ=64 (4 warps x 16 exclusive rows), BS=64. Epilogue writes fp16 [bh|bh] pack.
__global__ __launch_bounds__(128)
void attn_kernel(const __half* __restrict__ qh, const __half* __restrict__ khf,
                 const __half* __restrict__ vhf, const int* __restrict__ cposp,
                 __half* __restrict__ attnT){
    extern __shared__ __half smh[];
    const int TS = 64*136;
    const int tid=threadIdx.x, lane=tid&31, w=tid>>5;
    const int q0=blockIdx.x*64, h=blockIdx.y, kv=h>>1;
    const int cpos = cposp[0];
    const unsigned sb=(unsigned)__cvta_generic_to_shared(smh);
    const unsigned uQ=sb;
    const unsigned uKb[2] = { sb+TS*2,   sb+3*TS*2 };
    const unsigned uVb[2] = { sb+2*TS*2, sb+4*TS*2 };

    // Q tile (own cp.async group)
#pragma unroll
    for (int i=0;i<8;i++){
        int c = tid + i*128;
        int row = c>>4, seg = c&15;
        cpa16(uQ + (unsigned)((row*136 + seg*8)*2),
              qh + ((size_t)h*Q_ + q0 + row)*128 + seg*8);
    }
    CPC();

    auto ldkv = [&](int sbk, int buf){
        int s0 = sbk*64;
#pragma unroll
        for (int i=0;i<8;i++){
            int c = tid + i*128;
            int row = c>>4, seg = c&15;
            size_t gk = ((size_t)kv*S_ + s0 + row)*128 + seg*8;
            unsigned so = (unsigned)((row*136 + seg*8)*2);
            cpa16(uKb[buf]+so, khf+gk);
            cpa16(uVb[buf]+so, vhf+gk);
        }
        CPC();
    };

    float out[16][4];
#pragma unroll
    for (int a=0;a<16;a++)
#pragma unroll
        for (int c=0;c<4;c++) out[a][c]=0.f;
    float m0=-1e30f, m1=-1e30f, l0=0.f, l1=0.f;
    const int r0 = lane>>2, qb = q0 + w*16;

    int nblk = (cpos + q0 + 63)/64 + 1;
    if (nblk > S_/64) nblk = S_/64;

    ldkv(0,0);

    for (int sbk=0; sbk<nblk; sbk++){
        const int s0 = sbk*64;
        const int b = sbk&1;
        if (sbk+1 < nblk){ ldkv(sbk+1, b^1); CPW1(); } else { CPW0(); }
        __syncthreads();
        const unsigned uK = uKb[b], uV = uVb[b];

        // ---- scores ----
        float sc[8][4];
#pragma unroll
        for (int a=0;a<8;a++)
#pragma unroll
            for (int c=0;c<4;c++) sc[a][c]=0.f;
#pragma unroll
        for (int kd=0;kd<8;kd++){
            unsigned aq[4];
            unsigned qo = (unsigned)(((w*16+(lane&15))*136 + kd*16 + (lane>>4)*8)*2);
            ldsm4(aq[0],aq[1],aq[2],aq[3], uQ+qo);
#pragma unroll
            for (int nt=0;nt<4;nt++){
                unsigned ko = (unsigned)(((nt*16+(lane&15))*136 + kd*16 + (lane>>4)*8)*2);
                unsigned k0r,k1r,k2r,k3r;
                ldsm4(k0r,k1r,k2r,k3r, uK+ko);
                mma_f16(sc[2*nt],   aq, k0r,k2r);
                mma_f16(sc[2*nt+1], aq, k1r,k3r);
            }
        }

        // ---- causal mask ----
        if (s0 + 63 > cpos + qb){
            int lim0 = cpos + qb + r0, lim1 = lim0 + 8;
#pragma unroll
            for (int nf=0;nf<8;nf++){
                int j = s0 + nf*8 + 2*(lane&3);
                if (j   > lim0) sc[nf][0] = -1e30f;
                if (j+1 > lim0) sc[nf][1] = -1e30f;
                if (j   > lim1) sc[nf][2] = -1e30f;
                if (j+1 > lim1) sc[nf][3] = -1e30f;
            }
        }

        // ---- online softmax ----
        float mx0=-1e30f, mx1=-1e30f;
#pragma unroll
        for (int nf=0;nf<8;nf++){
            mx0 = fmaxf(mx0, fmaxf(sc[nf][0], sc[nf][1]));
            mx1 = fmaxf(mx1, fmaxf(sc[nf][2], sc[nf][3]));
        }
        mx0 = fmaxf(mx0, __shfl_xor_sync(0xffffffffu, mx0, 1));
        mx0 = fmaxf(mx0, __shfl_xor_sync(0xffffffffu, mx0, 2));
        mx1 = fmaxf(mx1, __shfl_xor_sync(0xffffffffu, mx1, 1));
        mx1 = fmaxf(mx1, __shfl_xor_sync(0xffffffffu, mx1, 2));
        float n0_ = fmaxf(m0, mx0), n1_ = fmaxf(m1, mx1);
        float s0f = __expf(m0 - n0_), s1f = __expf(m1 - n1_);
        m0 = n0_; m1 = n1_;
        float ps0=0.f, ps1=0.f;
#pragma unroll
        for (int nf=0;nf<8;nf++){
            sc[nf][0]=__expf(sc[nf][0]-m0); ps0+=sc[nf][0];
            sc[nf][1]=__expf(sc[nf][1]-m0); ps0+=sc[nf][1];
            sc[nf][2]=__expf(sc[nf][2]-m1); ps1+=sc[nf][2];
            sc[nf][3]=__expf(sc[nf][3]-m1); ps1+=sc[nf][3];
        }
        ps0 += __shfl_xor_sync(0xffffffffu, ps0, 1);
        ps0 += __shfl_xor_sync(0xffffffffu, ps0, 2);
        ps1 += __shfl_xor_sync(0xffffffffu, ps1, 1);
        ps1 += __shfl_xor_sync(0xffffffffu, ps1, 2);
        l0 = l0*s0f + ps0;
        l1 = l1*s1f + ps1;
#pragma unroll
        for (int df=0;df<16;df++){
            out[df][0]*=s0f; out[df][1]*=s0f; out[df][2]*=s1f; out[df][3]*=s1f;
        }

        // ---- PV ----
#pragma unroll
        for (int kc=0;kc<4;kc++){
            unsigned ph[4];
            ph[0] = f2h2(sc[2*kc][0],   sc[2*kc][1]);
            ph[1] = f2h2(sc[2*kc][2],   sc[2*kc][3]);
            ph[2] = f2h2(sc[2*kc+1][0], sc[2*kc+1][1]);
            ph[3] = f2h2(sc[2*kc+1][2], sc[2*kc+1][3]);
#pragma unroll
            for (int dt=0;dt<8;dt++){
                unsigned vo = (unsigned)(((kc*16+(lane&15))*136 + dt*16 + (lane>>4)*8)*2);
                unsigned v0,v1,v2,v3;
                ldsm4t(v0,v1,v2,v3, uV+vo);
                mma_f16(out[2*dt],   ph, v0,v1);
                mma_f16(out[2*dt+1], ph, v2,v3);
            }
        }
        __syncthreads();   // all warps done reading buffer b before it is reloaded
    }

    // ---- epilogue: normalize, write fp16 Wo B-pack [bh|bh] ----
    float inv0 = 1.f/l0, inv1 = 1.f/l1;
    int qrow0 = qb + r0, qrow1 = qrow0 + 8;
#pragma unroll
    for (int df=0;df<16;df++){
        int colg = h*128 + df*8 + (lane&3)*2;
        unsigned hv;
        hv = f2h2(out[df][0]*inv0, out[df][1]*inv0);
        *(unsigned*)(attnT + (size_t)qrow0*K2_ + colg)        = hv;
        *(unsigned*)(attnT + (size_t)qrow0*K2_ + 2048 + colg) = hv;
        hv = f2h2(out[df][2]*inv1, out[df][3]*inv1);
        *(unsigned*)(attnT + (size_t)qrow1*K2_ + colg)        = hv;
        *(unsigned*)(attnT + (size_t)qrow1*K2_ + 2048 + colg) = hv;
    }
}

// ---------------- launch ----------------
extern "C" void kernel_launch(void* const* d_in, const int* in_sizes, int n_in,
                              void* d_out, int out_size){
    const float* hidden = (const float*)d_in[0];
    const float* cosQD  = (const float*)d_in[1];
    const float* sinQD  = (const float*)d_in[2];
    const float* kcache = (const float*)d_in[6];
    const float* vcache = (const float*)d_in[7];
    const float* Wq = (const float*)d_in[8];
    const float* bq = (const float*)d_in[9];
    const float* Wk = (const float*)d_in[10];
    const float* bk = (const float*)d_in[11];
    const float* Wv = (const float*)d_in[12];
    const float* bv = (const float*)d_in[13];
    const float* Wo = (const float*)d_in[14];
    const int* cpos = (const int*)d_in[15];
    float* out = (float*)d_out;

    float *pqkv,*pkn,*pvn;
    __half *pqh,*pkhf,*pvhf,*pWqkv,*pWo,*pHid,*pAtt;
    cudaGetSymbolAddress((void**)&pqkv,g_qkv);
    cudaGetSymbolAddress((void**)&pkn,g_knew);  cudaGetSymbolAddress((void**)&pvn,g_vnew);
    cudaGetSymbolAddress((void**)&pqh,g_qh);
    cudaGetSymbolAddress((void**)&pkhf,g_khf);  cudaGetSymbolAddress((void**)&pvhf,g_vhf);
    cudaGetSymbolAddress((void**)&pWqkv,g_Wqkv);cudaGetSymbolAddress((void**)&pWo,g_WoPk);
    cudaGetSymbolAddress((void**)&pHid,g_hidT); cudaGetSymbolAddress((void**)&pAtt,g_attnT);

    // operand prep (fused QKV weight pack at row offsets 0 / 2048 / 3072)
    splitA_kernel<<<(HID_*HID_/4)/256, 256>>>(Wq, pWqkv, HID_*HID_/4);
    splitA_kernel<<<(KV_*D_*HID_/4)/256, 256>>>(Wk, pWqkv + (size_t)2048*K2_, KV_*D_*HID_/4);
    splitA_kernel<<<(KV_*D_*HID_/4)/256, 256>>>(Wv, pWqkv + (size_t)3072*K2_, KV_*D_*HID_/4);
    splitA_kernel<<<(HID_*HID_/4)/256, 256>>>(Wo, pWo, HID_*HID_/4);
    transpose_splitB_kernel<<<dim3(Q_/32, HID_/32), dim3(32,8)>>>(hidden, pHid);

    // fused QKV projection (M=4096) on fp16 HMMA
    gemm_pk_kernel<<<dim3(8,32), 256>>>(pWqkv, pHid, bq, bk, bv, pqkv);

    // RoPE (+fp16 for Q, folding 1/sqrt(D))
    rope_q_fp16_kernel<<<dim3(Q_/32, H_), dim3(32,8)>>>(pqkv, cosQD, sinQD, pqh, 0.08838834764831845f);
    rope_transpose_kernel<<<dim3(Q_/32, KV_), dim3(32,8)>>>(pqkv + (size_t)2048*Q_, cosQD, sinQD, pkn, 1);
    rope_transpose_kernel<<<dim3(Q_/32, KV_), dim3(32,8)>>>(pqkv + (size_t)3072*Q_, nullptr, nullptr, pvn, 0);

    // merged KV -> fp16
    merge_kv_fp16_kernel<<<(KV_*S_*D_/4)/256, 256>>>(kcache, vcache, pkn, pvn, cpos, pkhf, pvhf);

    // flash attention (fp16, double-buffered K/V)
    const int ATTN_SMEM = 5*64*136*2;   // 87040 B
    cudaFuncSetAttribute(attn_kernel, cudaFuncAttributeMaxDynamicSharedMemorySize, ATTN_SMEM);
    attn_kernel<<<dim3(Q_/64, H_), 128, ATTN_SMEM>>>(pqh, pkhf, pvhf, cpos, pAtt);

    // output projection on fp16 HMMA (no bias)
    gemm_pk_kernel<<<dim3(8,16), 256>>>(pWo, pAtt, nullptr, nullptr, nullptr, out);
}

// round 11
// speedup vs baseline: 5.8857x; 1.0128x over previous
#include <cuda_runtime.h>
#include <cuda_bf16.h>
#include <cuda_fp16.h>
#include <math.h>

#define H_   16
#define KV_  8
#define D_   128
#define HID_ 2048
#define Q_   1024
#define S_   8192
#define K2_  4096

// ---------------- device-global scratch ----------------
__device__ float  g_qkv[4096 * Q_];            // fused QKV projection [4096][1024] fp32
__device__ __half g_qh [H_*Q_*D_];             // fp16 Q, RoPE'd, scaled
__device__ __half g_khf[KV_*S_*D_];            // fp16 merged K (cache + new)
__device__ __half g_vhf[KV_*S_*D_];            // fp16 merged V
__device__ __half g_Wqkv[(size_t)4096*K2_];    // A-pack [ah|al] of 64*W
__device__ __half g_WoPk[(size_t)HID_*K2_];
__device__ __half g_hidT[(size_t)Q_*K2_];      // B-pack [bh|bh]
__device__ __half g_attnT[(size_t)Q_*K2_];     // B-pack [bh|bh]

// ---------------- PTX helpers ----------------
__device__ __forceinline__ void ldsm4(unsigned &r0,unsigned &r1,unsigned &r2,unsigned &r3,unsigned a){
    asm volatile("ldmatrix.sync.aligned.m8n8.x4.shared.b16 {%0,%1,%2,%3},[%4];"
                 :"=r"(r0),"=r"(r1),"=r"(r2),"=r"(r3):"r"(a));
}
__device__ __forceinline__ void ldsm4t(unsigned &r0,unsigned &r1,unsigned &r2,unsigned &r3,unsigned a){
    asm volatile("ldmatrix.sync.aligned.m8n8.x4.trans.shared.b16 {%0,%1,%2,%3},[%4];"
                 :"=r"(r0),"=r"(r1),"=r"(r2),"=r"(r3):"r"(a));
}
__device__ __forceinline__ void mma_f16(float c[4], const unsigned a[4], unsigned b0, unsigned b1){
    asm volatile("mma.sync.aligned.m16n8k16.row.col.f32.f16.f16.f32 "
                 "{%0,%1,%2,%3},{%4,%5,%6,%7},{%8,%9},{%0,%1,%2,%3};"
                 :"+f"(c[0]),"+f"(c[1]),"+f"(c[2]),"+f"(c[3])
                 :"r"(a[0]),"r"(a[1]),"r"(a[2]),"r"(a[3]),"r"(b0),"r"(b1));
}
__device__ __forceinline__ void cpa16(unsigned s, const void* g){
    asm volatile("cp.async.cg.shared.global [%0],[%1],16;"::"r"(s),"l"(g));
}
#define CPC()  asm volatile("cp.async.commit_group;")
#define CPW0() asm volatile("cp.async.wait_group 0;")
#define CPW1() asm volatile("cp.async.wait_group 1;")

__device__ __forceinline__ unsigned f2h2(float x, float y){
    __half2 h = __floats2half2_rn(x,y); return *reinterpret_cast<unsigned*>(&h);
}
__device__ __forceinline__ void hilo2h(float x, float y, unsigned &hi, unsigned &lo){
    __half hx=__float2half_rn(x), hy=__float2half_rn(y);
    __half2 hp=__halves2half2(hx,hy); hi=*reinterpret_cast<unsigned*>(&hp);
    __half lx=__float2half_rn(x-__half2float(hx));
    __half ly=__float2half_rn(y-__half2float(hy));
    __half2 lp=__halves2half2(lx,ly); lo=*reinterpret_cast<unsigned*>(&lp);
}

// ---------------- prep: ALL weight A-packs in one launch ----------------
// float4 regions (FIXED sizes): Wq [0,1048576), Wk [1048576,1572864),
// Wv [1572864,2097152), Wo [2097152,3145728). 3072 blocks x 256 thr x 4 float4.
// All boundaries are multiples of 1024, so a block never straddles regions.
__global__ __launch_bounds__(256)
void splitA_all_kernel(const float* __restrict__ Wq, const float* __restrict__ Wk,
                       const float* __restrict__ Wv, const float* __restrict__ Wo,
                       __half* __restrict__ qkvPk, __half* __restrict__ woPk){
    const size_t base = (size_t)blockIdx.x * 1024;
    const int t = threadIdx.x;
#pragma unroll
    for (int j=0;j<4;j++){
        size_t f = base + j*256 + t;
        const float* src; __half* dst; size_t local;
        if (f < 1048576u)      { src=Wq; dst=qkvPk;                  local=f; }
        else if (f < 1572864u) { src=Wk; dst=qkvPk+(size_t)2048*K2_; local=f-1048576u; }
        else if (f < 2097152u) { src=Wv; dst=qkvPk+(size_t)3072*K2_; local=f-1572864u; }
        else                   { src=Wo; dst=woPk;                   local=f-2097152u; }
        size_t lin = local*4;
        int col = (int)(lin & (HID_-1));
        size_t row = lin >> 11;
        float4 w = *(const float4*)(src + lin);
        unsigned h0,l0,h1,l1;
        hilo2h(w.x*64.f, w.y*64.f, h0, l0);
        hilo2h(w.z*64.f, w.w*64.f, h1, l1);
        size_t b = row*K2_ + col;
        *(uint2*)(dst+b)      = make_uint2(h0,h1);
        *(uint2*)(dst+b+HID_) = make_uint2(l0,l1);
    }
}

// ---------------- prep: hidden [2048][1024] -> hidT B-pack [bh|bh] ----------------
__global__ __launch_bounds__(256)
void transpose_splitB_kernel(const float* __restrict__ src, __half* __restrict__ dst){
    __shared__ float t[32][33];
    const int tx=threadIdx.x, ty=threadIdx.y;          // 32 x 8
    const int n0=blockIdx.x*32, k0=blockIdx.y*32;
#pragma unroll
    for (int r=0;r<4;r++)
        t[ty+8*r][tx] = src[(size_t)(k0+ty+8*r)*Q_ + n0+tx];
    __syncthreads();
#pragma unroll
    for (int r=0;r<4;r++){
        int n = ty+8*r;
        __half hb = __float2half_rn(t[tx][n]);
        size_t b = (size_t)(n0+n)*K2_ + k0+tx;
        dst[b]=hb; dst[b+HID_]=hb;
    }
}

// ---------------- packed-K fp16 GEMM: C[M][1024] = (A/64)[M][4096]*B[1024][4096]^T (+bias) ----------------
__global__ __launch_bounds__(256)
void gemm_pk_kernel(const __half* __restrict__ A, const __half* __restrict__ B,
                    const float* __restrict__ b0, const float* __restrict__ b1,
                    const float* __restrict__ b2, float* __restrict__ C){
    __shared__ __half sA[2][128*40];
    __shared__ __half sB[2][128*40];
    const int tid=threadIdx.x, lane=tid&31, warp=tid>>5;
    const int wm = warp>>1, wn = warp&1;
    const int m0 = blockIdx.y*128, n0 = blockIdx.x*128;
    const unsigned uA=(unsigned)__cvta_generic_to_shared(&sA[0][0]);
    const unsigned uB=(unsigned)__cvta_generic_to_shared(&sB[0][0]);

    float acc[2][8][4];
#pragma unroll
    for (int a=0;a<2;a++)
#pragma unroll
        for (int b=0;b<8;b++)
#pragma unroll
            for (int c=0;c<4;c++) acc[a][b][c]=0.f;

    auto load=[&](int st,int k0){
#pragma unroll
        for (int i=0;i<2;i++){
            int c = tid + i*256;
            int row = c>>2, seg = c&3;
            cpa16(uA + (st*5120 + row*40 + seg*8)*2, A + (size_t)(m0+row)*K2_ + k0 + seg*8);
            cpa16(uB + (st*5120 + row*40 + seg*8)*2, B + (size_t)(n0+row)*K2_ + k0 + seg*8);
        }
    };
    load(0,0); CPC();

    for (int kt=0;kt<128;kt++){
        int st = kt&1;
        if (kt<127){ load(st^1,(kt+1)*32); CPC(); CPW1(); } else { CPW0(); }
        __syncthreads();
#pragma unroll
        for (int kh=0;kh<2;kh++){
            unsigned a0[4], a1[4];
            unsigned ao = (unsigned)((st*5120 + (wm*32+(lane&15))*40 + kh*16 + (lane>>4)*8)*2);
            ldsm4(a0[0],a0[1],a0[2],a0[3], uA+ao);
            ldsm4(a1[0],a1[1],a1[2],a1[3], uA+ao + 16*40*2);
            unsigned bf_[8][2];
#pragma unroll
            for (int nt=0;nt<4;nt++){
                unsigned bo = (unsigned)((st*5120 + (wn*64+nt*16+(lane&15))*40 + kh*16 + (lane>>4)*8)*2);
                unsigned r0,r1,r2,r3;
                ldsm4(r0,r1,r2,r3, uB+bo);
                bf_[2*nt][0]=r0; bf_[2*nt][1]=r2; bf_[2*nt+1][0]=r1; bf_[2*nt+1][1]=r3;
            }
#pragma unroll
            for (int nf=0;nf<8;nf++){
                mma_f16(acc[0][nf], a0, bf_[nf][0], bf_[nf][1]);
                mma_f16(acc[1][nf], a1, bf_[nf][0], bf_[nf][1]);
            }
        }
        __syncthreads();
    }
    const float SC = 0.015625f;   // 1/64
#pragma unroll
    for (int mf=0;mf<2;mf++)
#pragma unroll
        for (int nf=0;nf<8;nf++){
            int row = m0 + wm*32 + mf*16 + (lane>>2);
            int col = n0 + wn*64 + nf*8 + (lane&3)*2;
            float bva = 0.f, bvb = 0.f;
            if (b0){
                int r2 = row + 8;
                bva = (row<2048)? b0[row] : ((row<3072)? b1[row-2048] : b2[row-3072]);
                bvb = (r2 <2048)? b0[r2]  : ((r2 <3072)? b1[r2 -2048] : b2[r2 -3072]);
            }
            C[(size_t)row*Q_ + col]       = acc[mf][nf][0]*SC + bva;
            C[(size_t)row*Q_ + col + 1]   = acc[mf][nf][1]*SC + bva;
            C[(size_t)(row+8)*Q_ + col]   = acc[mf][nf][2]*SC + bvb;
            C[(size_t)(row+8)*Q_ + col+1] = acc[mf][nf][3]*SC + bvb;
        }
}

// ---------------- fused RoPE: Q->g_qh, K/V new tokens -> cache slots (fp16) ----------------
// grid (Q_/32, 32): y<16 = q head; 16..23 = k (kv=y-16, RoPE); 24..31 = v (copy).
__global__ __launch_bounds__(256)
void rope_all_kernel(const float* __restrict__ qkv, const float* __restrict__ cosQD,
                     const float* __restrict__ sinQD, const int* __restrict__ cposp,
                     __half* __restrict__ qh, __half* __restrict__ khf,
                     __half* __restrict__ vhf){
    __shared__ float tile[128][33];
    const int tx=threadIdx.x, ty=threadIdx.y;          // 32 x 8
    const int i0=blockIdx.x*32, slot=blockIdx.y;
    const int cpos = cposp[0];

    int srcrow; __half* dst; size_t drow0; int do_rope; float scale;
    if (slot < 16){ srcrow = slot*128;            dst=qh;  drow0=(size_t)slot*Q_ + i0;        do_rope=1; scale=0.08838834764831845f; }
    else if (slot < 24){ int kv=slot-16; srcrow = 2048 + kv*128; dst=khf; drow0=(size_t)kv*S_ + cpos + i0; do_rope=1; scale=1.f; }
    else { int kv=slot-24; srcrow = 3072 + kv*128; dst=vhf; drow0=(size_t)kv*S_ + cpos + i0; do_rope=0; scale=1.f; }

#pragma unroll
    for (int r=0;r<16;r++)
        tile[r*8+ty][tx] = qkv[(size_t)(srcrow + r*8+ty)*Q_ + i0+tx];
    __syncthreads();
    const int t = ty*32+tx;
#pragma unroll
    for (int r=0;r<16;r++){
        int idx = r*256 + t;
        int d = idx & 127, i = idx >> 7;
        float v = tile[d][i], outv;
        if (do_rope){
            float o = (d<64) ? -tile[d+64][i] : tile[d-64][i];
            outv = (v*cosQD[(size_t)(i0+i)*128+d] + o*sinQD[(size_t)(i0+i)*128+d])*scale;
        } else outv = v;
        dst[(drow0 + i)*128 + d] = __float2half_rn(outv);
    }
}

// ---------------- cache-only fp16 conversion (skips [cpos, cpos+Q)) ----------------
__global__ __launch_bounds__(256)
void merge_cache_kernel(const float* __restrict__ kc_, const float* __restrict__ vc_,
                        const int* __restrict__ cposp,
                        __half* __restrict__ khf, __half* __restrict__ vhf){
    const int cpos = cposp[0];
    const size_t base = (size_t)blockIdx.x * 512;
#pragma unroll
    for (int j=0;j<2;j++){
        size_t idx = base + j*256 + threadIdx.x;         // float4 index
        size_t lin = idx*4;
        int s = (int)((lin>>7) & (S_-1));
        if (s >= cpos && s < cpos + Q_) continue;        // rope_all owns these slots
        float4 k4 = *(const float4*)(kc_+lin);
        float4 v4 = *(const float4*)(vc_+lin);
        *(uint2*)(khf+lin) = make_uint2(f2h2(k4.x,k4.y), f2h2(k4.z,k4.w));
        *(uint2*)(vhf+lin) = make_uint2(f2h2(v4.x,v4.y), f2h2(v4.z,v4.w));
    }
}

// ---------------- flash attention, fp16 MMA, double-buffered K/V ----------------
__global__ __launch_bounds__(128)
void attn_kernel(const __half* __restrict__ qh, const __half* __restrict__ khf,
                 const __half* __restrict__ vhf, const int* __restrict__ cposp,
                 __half* __restrict__ attnT){
    extern __shared__ __half smh[];
    const int TS = 64*136;
    const int tid=threadIdx.x, lane=tid&31, w=tid>>5;
    const int q0=blockIdx.x*64, h=blockIdx.y, kv=h>>1;
    const int cpos = cposp[0];
    const unsigned sb=(unsigned)__cvta_generic_to_shared(smh);
    const unsigned uQ=sb;
    const unsigned uKb[2] = { sb+TS*2,   sb+3*TS*2 };
    const unsigned uVb[2] = { sb+2*TS*2, sb+4*TS*2 };

#pragma unroll
    for (int i=0;i<8;i++){
        int c = tid + i*128;
        int row = c>>4, seg = c&15;
        cpa16(uQ + (unsigned)((row*136 + seg*8)*2),
              qh + ((size_t)h*Q_ + q0 + row)*128 + seg*8);
    }
    CPC();

    auto ldkv = [&](int sbk, int buf){
        int s0 = sbk*64;
#pragma unroll
        for (int i=0;i<8;i++){
            int c = tid + i*128;
            int row = c>>4, seg = c&15;
            size_t gk = ((size_t)kv*S_ + s0 + row)*128 + seg*8;
            unsigned so = (unsigned)((row*136 + seg*8)*2);
            cpa16(uKb[buf]+so, khf+gk);
            cpa16(uVb[buf]+so, vhf+gk);
        }
        CPC();
    };

    float out[16][4];
#pragma unroll
    for (int a=0;a<16;a++)
#pragma unroll
        for (int c=0;c<4;c++) out[a][c]=0.f;
    float m0=-1e30f, m1=-1e30f, l0=0.f, l1=0.f;
    const int r0 = lane>>2, qb = q0 + w*16;

    int nblk = (cpos + q0 + 63)/64 + 1;
    if (nblk > S_/64) nblk = S_/64;

    ldkv(0,0);

    for (int sbk=0; sbk<nblk; sbk++){
        const int s0 = sbk*64;
        const int b = sbk&1;
        if (sbk+1 < nblk){ ldkv(sbk+1, b^1); CPW1(); } else { CPW0(); }
        __syncthreads();
        const unsigned uK = uKb[b], uV = uVb[b];

        float sc[8][4];
#pragma unroll
        for (int a=0;a<8;a++)
#pragma unroll
            for (int c=0;c<4;c++) sc[a][c]=0.f;
#pragma unroll
        for (int kd=0;kd<8;kd++){
            unsigned aq[4];
            unsigned qo = (unsigned)(((w*16+(lane&15))*136 + kd*16 + (lane>>4)*8)*2);
            ldsm4(aq[0],aq[1],aq[2],aq[3], uQ+qo);
#pragma unroll
            for (int nt=0;nt<4;nt++){
                unsigned ko = (unsigned)(((nt*16+(lane&15))*136 + kd*16 + (lane>>4)*8)*2);
                unsigned k0r,k1r,k2r,k3r;
                ldsm4(k0r,k1r,k2r,k3r, uK+ko);
                mma_f16(sc[2*nt],   aq, k0r,k2r);
                mma_f16(sc[2*nt+1], aq, k1r,k3r);
            }
        }

        if (s0 + 63 > cpos + qb){
            int lim0 = cpos + qb + r0, lim1 = lim0 + 8;
#pragma unroll
            for (int nf=0;nf<8;nf++){
                int j = s0 + nf*8 + 2*(lane&3);
                if (j   > lim0) sc[nf][0] = -1e30f;
                if (j+1 > lim0) sc[nf][1] = -1e30f;
                if (j   > lim1) sc[nf][2] = -1e30f;
                if (j+1 > lim1) sc[nf][3] = -1e30f;
            }
        }

        float mx0=-1e30f, mx1=-1e30f;
#pragma unroll
        for (int nf=0;nf<8;nf++){
            mx0 = fmaxf(mx0, fmaxf(sc[nf][0], sc[nf][1]));
            mx1 = fmaxf(mx1, fmaxf(sc[nf][2], sc[nf][3]));
        }
        mx0 = fmaxf(mx0, __shfl_xor_sync(0xffffffffu, mx0, 1));
        mx0 = fmaxf(mx0, __shfl_xor_sync(0xffffffffu, mx0, 2));
        mx1 = fmaxf(mx1, __shfl_xor_sync(0xffffffffu, mx1, 1));
        mx1 = fmaxf(mx1, __shfl_xor_sync(0xffffffffu, mx1, 2));
        float n0_ = fmaxf(m0, mx0), n1_ = fmaxf(m1, mx1);
        float s0f = __expf(m0 - n0_), s1f = __expf(m1 - n1_);
        m0 = n0_; m1 = n1_;
        float ps0=0.f, ps1=0.f;
#pragma unroll
        for (int nf=0;nf<8;nf++){
            sc[nf][0]=__expf(sc[nf][0]-m0); ps0+=sc[nf][0];
            sc[nf][1]=__expf(sc[nf][1]-m0); ps0+=sc[nf][1];
            sc[nf][2]=__expf(sc[nf][2]-m1); ps1+=sc[nf][2];
            sc[nf][3]=__expf(sc[nf][3]-m1); ps1+=sc[nf][3];
        }
        ps0 += __shfl_xor_sync(0xffffffffu, ps0, 1);
        ps0 += __shfl_xor_sync(0xffffffffu, ps0, 2);
        ps1 += __shfl_xor_sync(0xffffffffu, ps1, 1);
        ps1 += __shfl_xor_sync(0xffffffffu, ps1, 2);
        l0 = l0*s0f + ps0;
        l1 = l1*s1f + ps1;
#pragma unroll
        for (int df=0;df<16;df++){
            out[df][0]*=s0f; out[df][1]*=s0f; out[df][2]*=s1f; out[df][3]*=s1f;
        }

#pragma unroll
        for (int kc=0;kc<4;kc++){
            unsigned ph[4];
            ph[0] = f2h2(sc[2*kc][0],   sc[2*kc][1]);
            ph[1] = f2h2(sc[2*kc][2],   sc[2*kc][3]);
            ph[2] = f2h2(sc[2*kc+1][0], sc[2*kc+1][1]);
            ph[3] = f2h2(sc[2*kc+1][2], sc[2*kc+1][3]);
#pragma unroll
            for (int dt=0;dt<8;dt++){
                unsigned vo = (unsigned)(((kc*16+(lane&15))*136 + dt*16 + (lane>>4)*8)*2);
                unsigned v0,v1,v2,v3;
                ldsm4t(v0,v1,v2,v3, uV+vo);
                mma_f16(out[2*dt],   ph, v0,v1);
                mma_f16(out[2*dt+1], ph, v2,v3);
            }
        }
        __syncthreads();
    }

    float inv0 = 1.f/l0, inv1 = 1.f/l1;
    int qrow0 = qb + r0, qrow1 = qrow0 + 8;
#pragma unroll
    for (int df=0;df<16;df++){
        int colg = h*128 + df*8 + (lane&3)*2;
        unsigned hv;
        hv = f2h2(out[df][0]*inv0, out[df][1]*inv0);
        *(unsigned*)(attnT + (size_t)qrow0*K2_ + colg)        = hv;
        *(unsigned*)(attnT + (size_t)qrow0*K2_ + 2048 + colg) = hv;
        hv = f2h2(out[df][2]*inv1, out[df][3]*inv1);
        *(unsigned*)(attnT + (size_t)qrow1*K2_ + colg)        = hv;
        *(unsigned*)(attnT + (size_t)qrow1*K2_ + 2048 + colg) = hv;
    }
}

// ---------------- launch ----------------
extern "C" void kernel_launch(void* const* d_in, const int* in_sizes, int n_in,
                              void* d_out, int out_size){
    const float* hidden = (const float*)d_in[0];
    const float* cosQD  = (const float*)d_in[1];
    const float* sinQD  = (const float*)d_in[2];
    const float* kcache = (const float*)d_in[6];
    const float* vcache = (const float*)d_in[7];
    const float* Wq = (const float*)d_in[8];
    const float* bq = (const float*)d_in[9];
    const float* Wk = (const float*)d_in[10];
    const float* bk = (const float*)d_in[11];
    const float* Wv = (const float*)d_in[12];
    const float* bv = (const float*)d_in[13];
    const float* Wo = (const float*)d_in[14];
    const int* cpos = (const int*)d_in[15];
    float* out = (float*)d_out;

    float *pqkv;
    __half *pqh,*pkhf,*pvhf,*pWqkv,*pWo,*pHid,*pAtt;
    cudaGetSymbolAddress((void**)&pqkv,g_qkv);
    cudaGetSymbolAddress((void**)&pqh,g_qh);
    cudaGetSymbolAddress((void**)&pkhf,g_khf);  cudaGetSymbolAddress((void**)&pvhf,g_vhf);
    cudaGetSymbolAddress((void**)&pWqkv,g_Wqkv);cudaGetSymbolAddress((void**)&pWo,g_WoPk);
    cudaGetSymbolAddress((void**)&pHid,g_hidT); cudaGetSymbolAddress((void**)&pAtt,g_attnT);

    // cache-only fp16 conversion (independent; runs first)
    merge_cache_kernel<<<(KV_*S_*D_/4)/512, 256>>>(kcache, vcache, cpos, pkhf, pvhf);

    // all weight packs in one launch (3145728 float4 total)
    splitA_all_kernel<<<3072, 256>>>(Wq, Wk, Wv, Wo, pWqkv, pWo);
    transpose_splitB_kernel<<<dim3(Q_/32, HID_/32), dim3(32,8)>>>(hidden, pHid);

    // fused QKV projection (M=4096) on fp16 HMMA
    gemm_pk_kernel<<<dim3(8,32), 256>>>(pWqkv, pHid, bq, bk, bv, pqkv);

    // fused RoPE: Q -> g_qh (fp16, scaled); K/V new tokens -> cache slots (fp16)
    rope_all_kernel<<<dim3(Q_/32, 32), dim3(32,8)>>>(pqkv, cosQD, sinQD, cpos, pqh, pkhf, pvhf);

    // flash attention (fp16, double-buffered K/V)
    const int ATTN_SMEM = 5*64*136*2;   // 87040 B
    cudaFuncSetAttribute(attn_kernel, cudaFuncAttributeMaxDynamicSharedMemorySize, ATTN_SMEM);
    attn_kernel<<<dim3(Q_/64, H_), 128, ATTN_SMEM>>>(pqh, pkhf, pvhf, cpos, pAtt);

    // output projection on fp16 HMMA (no bias)
    gemm_pk_kernel<<<dim3(8,16), 256>>>(pWo, pAtt, nullptr, nullptr, nullptr, out);
}